// round 4
// baseline (speedup 1.0000x reference)
#include <cuda_runtime.h>
#include <stdint.h>

// ---------------------------------------------------------------------------
// ShallowGCNet: 4x GCNConv(lrelu) + dropout + dense
// N=50000 nodes, E=800000 edges, features 256->256->256->128->64->10
// edge_index arrives as int32 (JAX x64 disabled; harness has no int64 path).
// ---------------------------------------------------------------------------

__device__ float g_bufA[50000 * 256];
__device__ float g_bufB[50000 * 256];
__device__ float g_dinv[50000];
__device__ int   g_deg[50000];

// ------------------------------ degree ------------------------------------
__global__ void deg_init_kernel(int n) {
  int i = blockIdx.x * blockDim.x + threadIdx.x;
  if (i < n) g_deg[i] = 1;  // self-loop
}
__global__ void deg_count_kernel(const int* __restrict__ dst, int E) {
  int e = blockIdx.x * blockDim.x + threadIdx.x;
  if (e < E) atomicAdd(&g_deg[dst[e]], 1);
}
__global__ void dinv_kernel(int n) {
  int i = blockIdx.x * blockDim.x + threadIdx.x;
  if (i < n) g_dinv[i] = 1.0f / sqrtf((float)g_deg[i]);
}

// ------------------------------ GEMM ---------------------------------------
// C[N,Fout] = act(A + preb) @ W   (pre-activation = bias+leakyrelu of the
// PREVIOUS layer, fused into the A-tile load). BM=128, BK=16, BN in {128,64}.
// 256 threads, 8x(4*NGJ) microtile per thread, spread layout (ty*4 / 64+ty*4).
template<int BN, bool PRE>
__global__ void __launch_bounds__(256, 2) gemm_kernel(
    const float* __restrict__ A, const float* __restrict__ W,
    const float* __restrict__ preb, float* __restrict__ C,
    int N, int K, int Fout) {
  constexpr int BM = 128, BK = 16;
  constexpr int NGJ = BN / 64;  // 2 for BN=128, 1 for BN=64
  __shared__ float As[BK][BM + 4];
  __shared__ float Ws[BK][BN + 4];
  const int tid = threadIdx.x;
  const int tx = tid & 15, ty = tid >> 4;
  const int row0 = blockIdx.x * BM;
  const int col0 = blockIdx.y * BN;

  float acc[8][NGJ * 4];
#pragma unroll
  for (int i = 0; i < 8; ++i)
#pragma unroll
    for (int j = 0; j < NGJ * 4; ++j) acc[i][j] = 0.f;

  for (int k0 = 0; k0 < K; k0 += BK) {
#pragma unroll
    for (int p = 0; p < (BM * BK) / 256; ++p) {
      int idx = tid + p * 256;
      int r = idx >> 4, kk = idx & 15;
      int grow = row0 + r;
      float v = 0.f;
      if (grow < N) v = A[(size_t)grow * K + (k0 + kk)];
      if (PRE) {
        v += preb[k0 + kk];
        v = (v > 0.f) ? v : 0.01f * v;
      }
      As[kk][r] = v;
    }
#pragma unroll
    for (int p = 0; p < (BK * BN) / 256; ++p) {
      int idx = tid + p * 256;
      int kk = idx / BN, c = idx % BN;
      Ws[kk][c] = W[(size_t)(k0 + kk) * Fout + (col0 + c)];
    }
    __syncthreads();
#pragma unroll
    for (int kk = 0; kk < BK; ++kk) {
      float a[8], b[NGJ * 4];
      *(float4*)&a[0] = *(const float4*)&As[kk][ty * 4];
      *(float4*)&a[4] = *(const float4*)&As[kk][64 + ty * 4];
      *(float4*)&b[0] = *(const float4*)&Ws[kk][tx * 4];
      if constexpr (NGJ == 2) {
        *(float4*)&b[4] = *(const float4*)&Ws[kk][64 + tx * 4];
      }
#pragma unroll
      for (int i = 0; i < 8; ++i)
#pragma unroll
        for (int j = 0; j < NGJ * 4; ++j) acc[i][j] += a[i] * b[j];
    }
    __syncthreads();
  }
#pragma unroll
  for (int gi = 0; gi < 2; ++gi) {
#pragma unroll
    for (int i = 0; i < 4; ++i) {
      int grow = row0 + gi * 64 + ty * 4 + i;
      if (grow >= N) continue;
#pragma unroll
      for (int gj = 0; gj < NGJ; ++gj) {
        float4 v = make_float4(acc[gi * 4 + i][gj * 4 + 0],
                               acc[gi * 4 + i][gj * 4 + 1],
                               acc[gi * 4 + i][gj * 4 + 2],
                               acc[gi * 4 + i][gj * 4 + 3]);
        *(float4*)&C[(size_t)grow * Fout + col0 + gj * 64 + tx * 4] = v;
      }
    }
  }
}

// --------------------------- aggregation -----------------------------------

// out[i] = dinv[i]^2 * tmp[i]   (self-loop term, also zero-initializes out)
template<int F>
__global__ void selfloop_kernel(const float* __restrict__ tmp,
                                float* __restrict__ out, int n) {
  int t = blockIdx.x * blockDim.x + threadIdx.x;
  int total = n * (F / 4);
  if (t >= total) return;
  int i = t / (F / 4);
  float w = g_dinv[i];
  w = w * w;
  float4 v = ((const float4*)tmp)[t];
  v.x *= w; v.y *= w; v.z *= w; v.w *= w;
  ((float4*)out)[t] = v;
}

// out[dst] += dinv[src]*dinv[dst] * tmp[src]  (scalar global reds)
template<int F>
__global__ void scatter_kernel(const float* __restrict__ tmp,
                               float* __restrict__ out,
                               const int* __restrict__ src,
                               const int* __restrict__ dst, int E) {
  constexpr int VEC = F / 4;
  constexpr int G = (VEC < 32) ? VEC : 32;  // lanes per edge
  constexpr int ITER = VEC / G;
  int t = blockIdx.x * blockDim.x + threadIdx.x;
  int e = t / G;
  int lane = t % G;
  if (e >= E) return;
  int s = src[e], d = dst[e];
  float norm = g_dinv[s] * g_dinv[d];
  const float4* trow = (const float4*)(tmp + (size_t)s * F);
  float* orow = out + (size_t)d * F;
#pragma unroll
  for (int it = 0; it < ITER; ++it) {
    int c = lane + it * G;
    float4 v = trow[c];
    atomicAdd(orow + c * 4 + 0, v.x * norm);
    atomicAdd(orow + c * 4 + 1, v.y * norm);
    atomicAdd(orow + c * 4 + 2, v.z * norm);
    atomicAdd(orow + c * 4 + 3, v.w * norm);
  }
}

// ------------------- dropout (JAX threefry) + dense -------------------------
// jax.random.bernoulli(key(42), 0.5, (N,64)) with threefry_partitionable=True:
// per element: threefry2x32(key=(0,42), x=(idx>>32, idx&0xffffffff));
// bits = out0 ^ out1; keep iff uniform<0.5 iff top bit of bits is 0.
#define TF_ROUND(x0, x1, r)                         \
  { x0 += x1; x1 = (x1 << (r)) | (x1 >> (32 - (r))); x1 ^= x0; }

__device__ __forceinline__ uint32_t threefry_bits(uint32_t idx) {
  const uint32_t k0 = 0u, k1 = 42u;
  const uint32_t k2 = 0x1BD11BDAu ^ k0 ^ k1;
  uint32_t x0 = 0u, x1 = idx;  // (counts_hi, counts_lo); hi==0 (idx < 2^32)
  x0 += k0; x1 += k1;
  TF_ROUND(x0, x1, 13) TF_ROUND(x0, x1, 15) TF_ROUND(x0, x1, 26) TF_ROUND(x0, x1, 6)
  x0 += k1; x1 += k2 + 1u;
  TF_ROUND(x0, x1, 17) TF_ROUND(x0, x1, 29) TF_ROUND(x0, x1, 16) TF_ROUND(x0, x1, 24)
  x0 += k2; x1 += k0 + 2u;
  TF_ROUND(x0, x1, 13) TF_ROUND(x0, x1, 15) TF_ROUND(x0, x1, 26) TF_ROUND(x0, x1, 6)
  x0 += k0; x1 += k1 + 3u;
  TF_ROUND(x0, x1, 17) TF_ROUND(x0, x1, 29) TF_ROUND(x0, x1, 16) TF_ROUND(x0, x1, 24)
  x0 += k1; x1 += k2 + 4u;
  TF_ROUND(x0, x1, 13) TF_ROUND(x0, x1, 15) TF_ROUND(x0, x1, 26) TF_ROUND(x0, x1, 6)
  x0 += k2; x1 += k0 + 5u;
  return x0 ^ x1;
}

// out[N,10] = dropout(lrelu(h + b4)) @ W5 + b5.  One warp per node row.
__global__ void final_kernel(const float* __restrict__ h,
                             const float* __restrict__ b4,
                             const float* __restrict__ W5,
                             const float* __restrict__ b5,
                             float* __restrict__ out, int n) {
  __shared__ float w5s[640];
  __shared__ float b5s[16];
  for (int i = threadIdx.x; i < 640; i += blockDim.x) w5s[i] = W5[i];
  if (threadIdx.x < 10) b5s[threadIdx.x] = b5[threadIdx.x];
  __syncthreads();
  int gw = (blockIdx.x * blockDim.x + threadIdx.x) >> 5;
  int lane = threadIdx.x & 31;
  if (gw >= n) return;
  int i = gw;
  float v0 = h[i * 64 + lane] + b4[lane];
  v0 = (v0 > 0.f) ? v0 : 0.01f * v0;
  float v1 = h[i * 64 + lane + 32] + b4[lane + 32];
  v1 = (v1 > 0.f) ? v1 : 0.01f * v1;
  uint32_t bits0 = threefry_bits((uint32_t)(i * 64 + lane));
  uint32_t bits1 = threefry_bits((uint32_t)(i * 64 + lane + 32));
  v0 = (bits0 & 0x80000000u) ? 0.f : v0 * 2.f;
  v1 = (bits1 & 0x80000000u) ? 0.f : v1 * 2.f;
#pragma unroll
  for (int j = 0; j < 10; ++j) {
    float p = v0 * w5s[lane * 10 + j] + v1 * w5s[(lane + 32) * 10 + j];
#pragma unroll
    for (int off = 16; off; off >>= 1)
      p += __shfl_xor_sync(0xffffffffu, p, off);
    if (lane == 0) out[i * 10 + j] = p + b5s[j];
  }
}

// ------------------------------ launch -------------------------------------
extern "C" void kernel_launch(void* const* d_in, const int* in_sizes, int n_in,
                              void* d_out, int out_size) {
  const float* x = (const float*)d_in[0];
  const int* ei = (const int*)d_in[1];   // int32! (JAX x64 disabled)
  const float* W1 = (const float*)d_in[2];
  const float* b1 = (const float*)d_in[3];
  const float* W2 = (const float*)d_in[4];
  const float* b2 = (const float*)d_in[5];
  const float* W3 = (const float*)d_in[6];
  const float* b3 = (const float*)d_in[7];
  const float* W4 = (const float*)d_in[8];
  const float* b4 = (const float*)d_in[9];
  const float* W5 = (const float*)d_in[10];
  const float* b5 = (const float*)d_in[11];
  const int N = in_sizes[0] / 256;
  const int E = in_sizes[1] / 2;
  const int* src = ei;
  const int* dstp = ei + E;

  float* bufA = nullptr;
  float* bufB = nullptr;
  cudaGetSymbolAddress((void**)&bufA, g_bufA);
  cudaGetSymbolAddress((void**)&bufB, g_bufB);

  // normalization
  deg_init_kernel<<<(N + 255) / 256, 256>>>(N);
  deg_count_kernel<<<(E + 255) / 256, 256>>>(dstp, E);
  dinv_kernel<<<(N + 255) / 256, 256>>>(N);

  dim3 gA((N + 127) / 128, 2);  // Fout=256
  dim3 gB((N + 127) / 128, 1);  // Fout=128 / 64

  // L1: 256->256
  gemm_kernel<128, false><<<gA, 256>>>(x, W1, nullptr, bufA, N, 256, 256);
  selfloop_kernel<256><<<(N * 64 + 255) / 256, 256>>>(bufA, bufB, N);
  scatter_kernel<256><<<(E * 32 + 255) / 256, 256>>>(bufA, bufB, src, dstp, E);

  // L2: 256->256  (b1 + lrelu fused into A-load)
  gemm_kernel<128, true><<<gA, 256>>>(bufB, W2, b1, bufA, N, 256, 256);
  selfloop_kernel<256><<<(N * 64 + 255) / 256, 256>>>(bufA, bufB, N);
  scatter_kernel<256><<<(E * 32 + 255) / 256, 256>>>(bufA, bufB, src, dstp, E);

  // L3: 256->128
  gemm_kernel<128, true><<<gB, 256>>>(bufB, W3, b2, bufA, N, 256, 128);
  selfloop_kernel<128><<<(N * 32 + 255) / 256, 256>>>(bufA, bufB, N);
  scatter_kernel<128><<<(E * 32 + 255) / 256, 256>>>(bufA, bufB, src, dstp, E);

  // L4: 128->64
  gemm_kernel<64, true><<<gB, 256>>>(bufB, W4, b3, bufA, N, 128, 64);
  selfloop_kernel<64><<<(N * 16 + 255) / 256, 256>>>(bufA, bufB, N);
  scatter_kernel<64><<<(E * 16 + 255) / 256, 256>>>(bufA, bufB, src, dstp, E);

  // bias4 + lrelu + dropout + dense 64->10
  final_kernel<<<(N * 32 + 255) / 256, 256>>>(bufB, b4, W5, b5, (float*)d_out, N);
}

// round 5
// speedup vs baseline: 1.7903x; 1.7903x over previous
#include <cuda_runtime.h>
#include <stdint.h>

// ---------------------------------------------------------------------------
// ShallowGCNet: 4x GCNConv(lrelu) + dropout + dense
// N=50000 nodes, E=800000 edges, features 256->256->256->128->64->10
// edge_index arrives as int32 (JAX x64 disabled).
// ---------------------------------------------------------------------------

__device__ float g_bufA[50000 * 256];
__device__ float g_bufB[50000 * 256];
__device__ float g_dinv[50000];
__device__ int   g_deg[50000];

// ------------------------------ degree ------------------------------------
__global__ void deg_init_kernel(int n) {
  int i = blockIdx.x * blockDim.x + threadIdx.x;
  if (i < n) g_deg[i] = 1;  // self-loop
}
__global__ void deg_count_kernel(const int* __restrict__ dst, int E) {
  int e = blockIdx.x * blockDim.x + threadIdx.x;
  if (e < E) atomicAdd(&g_deg[dst[e]], 1);
}
__global__ void dinv_kernel(int n) {
  int i = blockIdx.x * blockDim.x + threadIdx.x;
  if (i < n) g_dinv[i] = 1.0f / sqrtf((float)g_deg[i]);
}

// ------------------------------ GEMM ---------------------------------------
// C[N,Fout] = act(A + preb) @ W   (bias+leakyrelu of the PREVIOUS layer fused
// into the A-tile load). BM=128, BK=16, BN in {128,64}. 256 threads.
template<int BN, bool PRE>
__global__ void __launch_bounds__(256, 2) gemm_kernel(
    const float* __restrict__ A, const float* __restrict__ W,
    const float* __restrict__ preb, float* __restrict__ C,
    int N, int K, int Fout) {
  constexpr int BM = 128, BK = 16;
  constexpr int NGJ = BN / 64;  // 2 for BN=128, 1 for BN=64
  __shared__ float As[BK][BM + 4];
  __shared__ float Ws[BK][BN + 4];
  const int tid = threadIdx.x;
  const int tx = tid & 15, ty = tid >> 4;
  const int row0 = blockIdx.x * BM;
  const int col0 = blockIdx.y * BN;

  float acc[8][NGJ * 4];
#pragma unroll
  for (int i = 0; i < 8; ++i)
#pragma unroll
    for (int j = 0; j < NGJ * 4; ++j) acc[i][j] = 0.f;

  for (int k0 = 0; k0 < K; k0 += BK) {
#pragma unroll
    for (int p = 0; p < (BM * BK) / 256; ++p) {
      int idx = tid + p * 256;
      int r = idx >> 4, kk = idx & 15;
      int grow = row0 + r;
      float v = 0.f;
      if (grow < N) v = A[(size_t)grow * K + (k0 + kk)];
      if (PRE) {
        v += preb[k0 + kk];
        v = (v > 0.f) ? v : 0.01f * v;
      }
      As[kk][r] = v;
    }
#pragma unroll
    for (int p = 0; p < (BK * BN) / 256; ++p) {
      int idx = tid + p * 256;
      int kk = idx / BN, c = idx % BN;
      Ws[kk][c] = W[(size_t)(k0 + kk) * Fout + (col0 + c)];
    }
    __syncthreads();
#pragma unroll
    for (int kk = 0; kk < BK; ++kk) {
      float a[8], b[NGJ * 4];
      *(float4*)&a[0] = *(const float4*)&As[kk][ty * 4];
      *(float4*)&a[4] = *(const float4*)&As[kk][64 + ty * 4];
      *(float4*)&b[0] = *(const float4*)&Ws[kk][tx * 4];
      if constexpr (NGJ == 2) {
        *(float4*)&b[4] = *(const float4*)&Ws[kk][64 + tx * 4];
      }
#pragma unroll
      for (int i = 0; i < 8; ++i)
#pragma unroll
        for (int j = 0; j < NGJ * 4; ++j) acc[i][j] += a[i] * b[j];
    }
    __syncthreads();
  }
#pragma unroll
  for (int gi = 0; gi < 2; ++gi) {
#pragma unroll
    for (int i = 0; i < 4; ++i) {
      int grow = row0 + gi * 64 + ty * 4 + i;
      if (grow >= N) continue;
#pragma unroll
      for (int gj = 0; gj < NGJ; ++gj) {
        float4 v = make_float4(acc[gi * 4 + i][gj * 4 + 0],
                               acc[gi * 4 + i][gj * 4 + 1],
                               acc[gi * 4 + i][gj * 4 + 2],
                               acc[gi * 4 + i][gj * 4 + 3]);
        *(float4*)&C[(size_t)grow * Fout + col0 + gj * 64 + tx * 4] = v;
      }
    }
  }
}

// --------------------------- aggregation -----------------------------------

// out[i] = dinv[i]^2 * tmp[i]   (self-loop term, also zero-initializes out)
template<int F>
__global__ void selfloop_kernel(const float* __restrict__ tmp,
                                float* __restrict__ out, int n) {
  int t = blockIdx.x * blockDim.x + threadIdx.x;
  int total = n * (F / 4);
  if (t >= total) return;
  int i = t / (F / 4);
  float w = g_dinv[i];
  w = w * w;
  float4 v = ((const float4*)tmp)[t];
  v.x *= w; v.y *= w; v.z *= w; v.w *= w;
  ((float4*)out)[t] = v;
}

// Vectorized global reduction (sm_90+ PTX). Round-1 trap was re-attributed to
// the int64 index bug; with sane global addresses this is the supported path.
__device__ __forceinline__ void red_add_v4(float* addr, float4 v) {
  asm volatile("red.global.add.v4.f32 [%0], {%1, %2, %3, %4};"
               :: "l"(addr), "f"(v.x), "f"(v.y), "f"(v.z), "f"(v.w)
               : "memory");
}

// out[dst] += dinv[src]*dinv[dst] * tmp[src]
template<int F>
__global__ void scatter_kernel(const float* __restrict__ tmp,
                               float* __restrict__ out,
                               const int* __restrict__ src,
                               const int* __restrict__ dst, int E) {
  constexpr int VEC = F / 4;
  constexpr int G = (VEC < 32) ? VEC : 32;  // lanes per edge
  constexpr int ITER = VEC / G;
  int t = blockIdx.x * blockDim.x + threadIdx.x;
  int e = t / G;
  int lane = t % G;
  if (e >= E) return;
  int s = src[e], d = dst[e];
  float norm = g_dinv[s] * g_dinv[d];
  const float4* trow = (const float4*)(tmp + (size_t)s * F);
  float* orow = out + (size_t)d * F;
#pragma unroll
  for (int it = 0; it < ITER; ++it) {
    int c = lane + it * G;
    float4 v = trow[c];
    v.x *= norm; v.y *= norm; v.z *= norm; v.w *= norm;
    red_add_v4(orow + c * 4, v);
  }
}

// ------------------- dropout (JAX threefry) + dense -------------------------
#define TF_ROUND(x0, x1, r)                         \
  { x0 += x1; x1 = (x1 << (r)) | (x1 >> (32 - (r))); x1 ^= x0; }

__device__ __forceinline__ uint32_t threefry_bits(uint32_t idx) {
  const uint32_t k0 = 0u, k1 = 42u;
  const uint32_t k2 = 0x1BD11BDAu ^ k0 ^ k1;
  uint32_t x0 = 0u, x1 = idx;
  x0 += k0; x1 += k1;
  TF_ROUND(x0, x1, 13) TF_ROUND(x0, x1, 15) TF_ROUND(x0, x1, 26) TF_ROUND(x0, x1, 6)
  x0 += k1; x1 += k2 + 1u;
  TF_ROUND(x0, x1, 17) TF_ROUND(x0, x1, 29) TF_ROUND(x0, x1, 16) TF_ROUND(x0, x1, 24)
  x0 += k2; x1 += k0 + 2u;
  TF_ROUND(x0, x1, 13) TF_ROUND(x0, x1, 15) TF_ROUND(x0, x1, 26) TF_ROUND(x0, x1, 6)
  x0 += k0; x1 += k1 + 3u;
  TF_ROUND(x0, x1, 17) TF_ROUND(x0, x1, 29) TF_ROUND(x0, x1, 16) TF_ROUND(x0, x1, 24)
  x0 += k1; x1 += k2 + 4u;
  TF_ROUND(x0, x1, 13) TF_ROUND(x0, x1, 15) TF_ROUND(x0, x1, 26) TF_ROUND(x0, x1, 6)
  x0 += k2; x1 += k0 + 5u;
  return x0 ^ x1;
}

// out[N,10] = dropout(lrelu(h + b4)) @ W5 + b5.  One warp per node row.
__global__ void final_kernel(const float* __restrict__ h,
                             const float* __restrict__ b4,
                             const float* __restrict__ W5,
                             const float* __restrict__ b5,
                             float* __restrict__ out, int n) {
  __shared__ float w5s[640];
  __shared__ float b5s[16];
  for (int i = threadIdx.x; i < 640; i += blockDim.x) w5s[i] = W5[i];
  if (threadIdx.x < 10) b5s[threadIdx.x] = b5[threadIdx.x];
  __syncthreads();
  int gw = (blockIdx.x * blockDim.x + threadIdx.x) >> 5;
  int lane = threadIdx.x & 31;
  if (gw >= n) return;
  int i = gw;
  float v0 = h[i * 64 + lane] + b4[lane];
  v0 = (v0 > 0.f) ? v0 : 0.01f * v0;
  float v1 = h[i * 64 + lane + 32] + b4[lane + 32];
  v1 = (v1 > 0.f) ? v1 : 0.01f * v1;
  uint32_t bits0 = threefry_bits((uint32_t)(i * 64 + lane));
  uint32_t bits1 = threefry_bits((uint32_t)(i * 64 + lane + 32));
  v0 = (bits0 & 0x80000000u) ? 0.f : v0 * 2.f;
  v1 = (bits1 & 0x80000000u) ? 0.f : v1 * 2.f;
#pragma unroll
  for (int j = 0; j < 10; ++j) {
    float p = v0 * w5s[lane * 10 + j] + v1 * w5s[(lane + 32) * 10 + j];
#pragma unroll
    for (int off = 16; off; off >>= 1)
      p += __shfl_xor_sync(0xffffffffu, p, off);
    if (lane == 0) out[i * 10 + j] = p + b5s[j];
  }
}

// ------------------------------ launch -------------------------------------
extern "C" void kernel_launch(void* const* d_in, const int* in_sizes, int n_in,
                              void* d_out, int out_size) {
  const float* x = (const float*)d_in[0];
  const int* ei = (const int*)d_in[1];   // int32
  const float* W1 = (const float*)d_in[2];
  const float* b1 = (const float*)d_in[3];
  const float* W2 = (const float*)d_in[4];
  const float* b2 = (const float*)d_in[5];
  const float* W3 = (const float*)d_in[6];
  const float* b3 = (const float*)d_in[7];
  const float* W4 = (const float*)d_in[8];
  const float* b4 = (const float*)d_in[9];
  const float* W5 = (const float*)d_in[10];
  const float* b5 = (const float*)d_in[11];
  const int N = in_sizes[0] / 256;
  const int E = in_sizes[1] / 2;
  const int* src = ei;
  const int* dstp = ei + E;

  float* bufA = nullptr;
  float* bufB = nullptr;
  cudaGetSymbolAddress((void**)&bufA, g_bufA);
  cudaGetSymbolAddress((void**)&bufB, g_bufB);

  // normalization
  deg_init_kernel<<<(N + 255) / 256, 256>>>(N);
  deg_count_kernel<<<(E + 255) / 256, 256>>>(dstp, E);
  dinv_kernel<<<(N + 255) / 256, 256>>>(N);

  dim3 gA((N + 127) / 128, 2);  // Fout=256
  dim3 gB((N + 127) / 128, 1);  // Fout=128 / 64

  // L1: 256->256
  gemm_kernel<128, false><<<gA, 256>>>(x, W1, nullptr, bufA, N, 256, 256);
  selfloop_kernel<256><<<(N * 64 + 255) / 256, 256>>>(bufA, bufB, N);
  scatter_kernel<256><<<(E * 32 + 255) / 256, 256>>>(bufA, bufB, src, dstp, E);

  // L2: 256->256  (b1 + lrelu fused into A-load)
  gemm_kernel<128, true><<<gA, 256>>>(bufB, W2, b1, bufA, N, 256, 256);
  selfloop_kernel<256><<<(N * 64 + 255) / 256, 256>>>(bufA, bufB, N);
  scatter_kernel<256><<<(E * 32 + 255) / 256, 256>>>(bufA, bufB, src, dstp, E);

  // L3: 256->128
  gemm_kernel<128, true><<<gB, 256>>>(bufB, W3, b2, bufA, N, 256, 128);
  selfloop_kernel<128><<<(N * 32 + 255) / 256, 256>>>(bufA, bufB, N);
  scatter_kernel<128><<<(E * 32 + 255) / 256, 256>>>(bufA, bufB, src, dstp, E);

  // L4: 128->64
  gemm_kernel<64, true><<<gB, 256>>>(bufB, W4, b3, bufA, N, 128, 64);
  selfloop_kernel<64><<<(N * 16 + 255) / 256, 256>>>(bufA, bufB, N);
  scatter_kernel<64><<<(E * 16 + 255) / 256, 256>>>(bufA, bufB, src, dstp, E);

  // bias4 + lrelu + dropout + dense 64->10
  final_kernel<<<(N * 32 + 255) / 256, 256>>>(bufB, b4, W5, b5, (float*)d_out, N);
}

// round 7
// speedup vs baseline: 2.4054x; 1.3435x over previous
#include <cuda_runtime.h>
#include <stdint.h>

// ---------------------------------------------------------------------------
// ShallowGCNet: 4x GCNConv(lrelu) + dropout + dense
// N=50000 nodes, E=800000 edges, features 256->256->256->128->64->10
// Aggregation via CSR gather (no float atomics). GEMM: SIMT fp32 (tcgen05 is
// unavailable: harness compiles -arch=sm_100 without the 'a' suffix).
// ---------------------------------------------------------------------------

__device__ float g_bufA[50000 * 256];
__device__ float g_bufB[50000 * 256];
__device__ float g_dinv[50000];
__device__ int   g_deg[50000];     // edge count per dst (no self-loop)
__device__ int   g_off[50001];     // CSR row offsets
__device__ int   g_bsum[64];       // scan block sums
__device__ int   g_fill[50000];    // fill cursors
__device__ int   g_csr_src[800000];
__device__ float g_csr_w[800000];  // dinv[src] per edge

// ------------------------------ degree ------------------------------------
__global__ void deg_init_kernel(int n) {
  int i = blockIdx.x * blockDim.x + threadIdx.x;
  if (i < n) { g_deg[i] = 0; g_fill[i] = 0; }
}
__global__ void deg_count_kernel(const int* __restrict__ dst, int E) {
  int e = blockIdx.x * blockDim.x + threadIdx.x;
  if (e < E) atomicAdd(&g_deg[dst[e]], 1);
}
__global__ void dinv_kernel(int n) {
  int i = blockIdx.x * blockDim.x + threadIdx.x;
  if (i < n) g_dinv[i] = 1.0f / sqrtf((float)(g_deg[i] + 1));  // +1 self-loop
}

// ------------------------------ CSR build ----------------------------------
#define SCAN_BLK 1024
__global__ void scan1_kernel(int n) {
  __shared__ int sh[SCAN_BLK];
  int i = blockIdx.x * SCAN_BLK + threadIdx.x;
  int v = (i < n) ? g_deg[i] : 0;
  sh[threadIdx.x] = v;
  __syncthreads();
#pragma unroll
  for (int d = 1; d < SCAN_BLK; d <<= 1) {
    int t = (threadIdx.x >= d) ? sh[threadIdx.x - d] : 0;
    __syncthreads();
    sh[threadIdx.x] += t;
    __syncthreads();
  }
  if (i < n) g_off[i] = sh[threadIdx.x] - v;   // exclusive
  if (threadIdx.x == SCAN_BLK - 1) g_bsum[blockIdx.x] = sh[threadIdx.x];
}
__global__ void scan2_kernel(int nb) {  // single block, nb <= 64
  __shared__ int sh[64];
  int v = (threadIdx.x < nb) ? g_bsum[threadIdx.x] : 0;
  sh[threadIdx.x] = v;
  __syncthreads();
#pragma unroll
  for (int d = 1; d < 64; d <<= 1) {
    int t = (threadIdx.x >= d) ? sh[threadIdx.x - d] : 0;
    __syncthreads();
    sh[threadIdx.x] += t;
    __syncthreads();
  }
  if (threadIdx.x < nb) g_bsum[threadIdx.x] = sh[threadIdx.x] - v;  // exclusive
}
__global__ void scan3_kernel(int n, int E) {
  int i = blockIdx.x * blockDim.x + threadIdx.x;
  if (i < n) g_off[i] += g_bsum[i >> 10];
  if (i == n) g_off[n] = E;
}
__global__ void fill_kernel(const int* __restrict__ src,
                            const int* __restrict__ dst, int E) {
  int e = blockIdx.x * blockDim.x + threadIdx.x;
  if (e >= E) return;
  int s = src[e], d = dst[e];
  int pos = g_off[d] + atomicAdd(&g_fill[d], 1);
  g_csr_src[pos] = s;
  g_csr_w[pos] = g_dinv[s];
}

// ------------------------------ GEMM ---------------------------------------
// C[N,Fout] = act(A + preb) @ W  (prev layer's bias+lrelu fused into A load).
template<int BN, bool PRE>
__global__ void __launch_bounds__(256, 2) gemm_kernel(
    const float* __restrict__ A, const float* __restrict__ W,
    const float* __restrict__ preb, float* __restrict__ C,
    int N, int K, int Fout) {
  constexpr int BM = 128, BK = 16;
  constexpr int NGJ = BN / 64;
  __shared__ float As[BK][BM + 4];
  __shared__ float Ws[BK][BN + 4];
  const int tid = threadIdx.x;
  const int tx = tid & 15, ty = tid >> 4;
  const int row0 = blockIdx.x * BM;
  const int col0 = blockIdx.y * BN;

  float acc[8][NGJ * 4];
#pragma unroll
  for (int i = 0; i < 8; ++i)
#pragma unroll
    for (int j = 0; j < NGJ * 4; ++j) acc[i][j] = 0.f;

  for (int k0 = 0; k0 < K; k0 += BK) {
#pragma unroll
    for (int p = 0; p < (BM * BK) / 256; ++p) {
      int idx = tid + p * 256;
      int r = idx >> 4, kk = idx & 15;
      int grow = row0 + r;
      float v = 0.f;
      if (grow < N) v = A[(size_t)grow * K + (k0 + kk)];
      if (PRE) {
        v += preb[k0 + kk];
        v = (v > 0.f) ? v : 0.01f * v;
      }
      As[kk][r] = v;
    }
#pragma unroll
    for (int p = 0; p < (BK * BN) / 256; ++p) {
      int idx = tid + p * 256;
      int kk = idx / BN, c = idx % BN;
      Ws[kk][c] = W[(size_t)(k0 + kk) * Fout + (col0 + c)];
    }
    __syncthreads();
#pragma unroll
    for (int kk = 0; kk < BK; ++kk) {
      float a[8], b[NGJ * 4];
      *(float4*)&a[0] = *(const float4*)&As[kk][ty * 4];
      *(float4*)&a[4] = *(const float4*)&As[kk][64 + ty * 4];
      *(float4*)&b[0] = *(const float4*)&Ws[kk][tx * 4];
      if constexpr (NGJ == 2) {
        *(float4*)&b[4] = *(const float4*)&Ws[kk][64 + tx * 4];
      }
#pragma unroll
      for (int i = 0; i < 8; ++i)
#pragma unroll
        for (int j = 0; j < NGJ * 4; ++j) acc[i][j] += a[i] * b[j];
    }
    __syncthreads();
  }
#pragma unroll
  for (int gi = 0; gi < 2; ++gi) {
#pragma unroll
    for (int i = 0; i < 4; ++i) {
      int grow = row0 + gi * 64 + ty * 4 + i;
      if (grow >= N) continue;
#pragma unroll
      for (int gj = 0; gj < NGJ; ++gj) {
        float4 v = make_float4(acc[gi * 4 + i][gj * 4 + 0],
                               acc[gi * 4 + i][gj * 4 + 1],
                               acc[gi * 4 + i][gj * 4 + 2],
                               acc[gi * 4 + i][gj * 4 + 3]);
        *(float4*)&C[(size_t)grow * Fout + col0 + gj * 64 + tx * 4] = v;
      }
    }
  }
}

// ----------------------- CSR gather aggregation -----------------------------
// out[d] = dinv[d] * ( dinv[d]*h[d] + sum_{e: dst=d} dinv[s_e]*h[s_e] )
// One warp per dst row; edge metadata broadcast via shuffle.
template<int F>
__global__ void gather_kernel(const float* __restrict__ tmp,
                              float* __restrict__ out, int n) {
  int w = (blockIdx.x * blockDim.x + threadIdx.x) >> 5;
  int lane = threadIdx.x & 31;
  if (w >= n) return;
  int beg = g_off[w], end = g_off[w + 1];
  float dr = g_dinv[w];

  if constexpr (F >= 128) {
    constexpr int NV = F / 128;  // float4 per lane
    float4 acc[NV];
    const float4* self = (const float4*)(tmp + (size_t)w * F);
#pragma unroll
    for (int v = 0; v < NV; ++v) {
      float4 x = self[lane + 32 * v];
      acc[v] = make_float4(x.x * dr, x.y * dr, x.z * dr, x.w * dr);
    }
    for (int e0 = beg; e0 < end; e0 += 32) {
      int ne = min(32, end - e0);
      int s = 0; float ww = 0.f;
      if (lane < ne) { s = g_csr_src[e0 + lane]; ww = g_csr_w[e0 + lane]; }
      for (int j = 0; j < ne; ++j) {
        int sj = __shfl_sync(0xffffffffu, s, j);
        float wj = __shfl_sync(0xffffffffu, ww, j);
        const float4* sr = (const float4*)(tmp + (size_t)sj * F);
#pragma unroll
        for (int v = 0; v < NV; ++v) {
          float4 x = sr[lane + 32 * v];
          acc[v].x += wj * x.x; acc[v].y += wj * x.y;
          acc[v].z += wj * x.z; acc[v].w += wj * x.w;
        }
      }
    }
    float4* orow = (float4*)(out + (size_t)w * F);
#pragma unroll
    for (int v = 0; v < NV; ++v)
      orow[lane + 32 * v] = make_float4(acc[v].x * dr, acc[v].y * dr,
                                        acc[v].z * dr, acc[v].w * dr);
  } else {  // F == 64: one float2 per lane
    float2 acc;
    const float2* self = (const float2*)(tmp + (size_t)w * F);
    {
      float2 x = self[lane];
      acc = make_float2(x.x * dr, x.y * dr);
    }
    for (int e0 = beg; e0 < end; e0 += 32) {
      int ne = min(32, end - e0);
      int s = 0; float ww = 0.f;
      if (lane < ne) { s = g_csr_src[e0 + lane]; ww = g_csr_w[e0 + lane]; }
      for (int j = 0; j < ne; ++j) {
        int sj = __shfl_sync(0xffffffffu, s, j);
        float wj = __shfl_sync(0xffffffffu, ww, j);
        float2 x = ((const float2*)(tmp + (size_t)sj * F))[lane];
        acc.x += wj * x.x; acc.y += wj * x.y;
      }
    }
    ((float2*)(out + (size_t)w * F))[lane] =
        make_float2(acc.x * dr, acc.y * dr);
  }
}

// ------------------- dropout (JAX threefry) + dense -------------------------
#define TF_ROUND(x0, x1, r)                         \
  { x0 += x1; x1 = (x1 << (r)) | (x1 >> (32 - (r))); x1 ^= x0; }

__device__ __forceinline__ uint32_t threefry_bits(uint32_t idx) {
  const uint32_t k0 = 0u, k1 = 42u;
  const uint32_t k2 = 0x1BD11BDAu ^ k0 ^ k1;
  uint32_t x0 = 0u, x1 = idx;
  x0 += k0; x1 += k1;
  TF_ROUND(x0, x1, 13) TF_ROUND(x0, x1, 15) TF_ROUND(x0, x1, 26) TF_ROUND(x0, x1, 6)
  x0 += k1; x1 += k2 + 1u;
  TF_ROUND(x0, x1, 17) TF_ROUND(x0, x1, 29) TF_ROUND(x0, x1, 16) TF_ROUND(x0, x1, 24)
  x0 += k2; x1 += k0 + 2u;
  TF_ROUND(x0, x1, 13) TF_ROUND(x0, x1, 15) TF_ROUND(x0, x1, 26) TF_ROUND(x0, x1, 6)
  x0 += k0; x1 += k1 + 3u;
  TF_ROUND(x0, x1, 17) TF_ROUND(x0, x1, 29) TF_ROUND(x0, x1, 16) TF_ROUND(x0, x1, 24)
  x0 += k1; x1 += k2 + 4u;
  TF_ROUND(x0, x1, 13) TF_ROUND(x0, x1, 15) TF_ROUND(x0, x1, 26) TF_ROUND(x0, x1, 6)
  x0 += k2; x1 += k0 + 5u;
  return x0 ^ x1;
}

// out[N,10] = dropout(lrelu(h + b4)) @ W5 + b5.  One warp per node row.
__global__ void final_kernel(const float* __restrict__ h,
                             const float* __restrict__ b4,
                             const float* __restrict__ W5,
                             const float* __restrict__ b5,
                             float* __restrict__ out, int n) {
  __shared__ float w5s[640];
  __shared__ float b5s[16];
  for (int i = threadIdx.x; i < 640; i += blockDim.x) w5s[i] = W5[i];
  if (threadIdx.x < 10) b5s[threadIdx.x] = b5[threadIdx.x];
  __syncthreads();
  int gw = (blockIdx.x * blockDim.x + threadIdx.x) >> 5;
  int lane = threadIdx.x & 31;
  if (gw >= n) return;
  int i = gw;
  float v0 = h[i * 64 + lane] + b4[lane];
  v0 = (v0 > 0.f) ? v0 : 0.01f * v0;
  float v1 = h[i * 64 + lane + 32] + b4[lane + 32];
  v1 = (v1 > 0.f) ? v1 : 0.01f * v1;
  uint32_t bits0 = threefry_bits((uint32_t)(i * 64 + lane));
  uint32_t bits1 = threefry_bits((uint32_t)(i * 64 + lane + 32));
  v0 = (bits0 & 0x80000000u) ? 0.f : v0 * 2.f;
  v1 = (bits1 & 0x80000000u) ? 0.f : v1 * 2.f;
#pragma unroll
  for (int j = 0; j < 10; ++j) {
    float p = v0 * w5s[lane * 10 + j] + v1 * w5s[(lane + 32) * 10 + j];
#pragma unroll
    for (int off = 16; off; off >>= 1)
      p += __shfl_xor_sync(0xffffffffu, p, off);
    if (lane == 0) out[i * 10 + j] = p + b5s[j];
  }
}

// ------------------------------ launch -------------------------------------
extern "C" void kernel_launch(void* const* d_in, const int* in_sizes, int n_in,
                              void* d_out, int out_size) {
  const float* x = (const float*)d_in[0];
  const int* ei = (const int*)d_in[1];   // int32
  const float* W1 = (const float*)d_in[2];
  const float* b1 = (const float*)d_in[3];
  const float* W2 = (const float*)d_in[4];
  const float* b2 = (const float*)d_in[5];
  const float* W3 = (const float*)d_in[6];
  const float* b3 = (const float*)d_in[7];
  const float* W4 = (const float*)d_in[8];
  const float* b4 = (const float*)d_in[9];
  const float* W5 = (const float*)d_in[10];
  const float* b5 = (const float*)d_in[11];
  const int N = in_sizes[0] / 256;
  const int E = in_sizes[1] / 2;
  const int* src = ei;
  const int* dstp = ei + E;

  float* bufA = nullptr;
  float* bufB = nullptr;
  cudaGetSymbolAddress((void**)&bufA, g_bufA);
  cudaGetSymbolAddress((void**)&bufB, g_bufB);

  // ---- normalization + CSR build ----
  deg_init_kernel<<<(N + 255) / 256, 256>>>(N);
  deg_count_kernel<<<(E + 255) / 256, 256>>>(dstp, E);
  dinv_kernel<<<(N + 255) / 256, 256>>>(N);
  int nblk = (N + SCAN_BLK - 1) / SCAN_BLK;
  scan1_kernel<<<nblk, SCAN_BLK>>>(N);
  scan2_kernel<<<1, 64>>>(nblk);
  scan3_kernel<<<(N + 256) / 256, 256>>>(N, E);
  fill_kernel<<<(E + 255) / 256, 256>>>(src, dstp, E);

  dim3 gA((N + 127) / 128, 2);  // Fout=256
  dim3 gB((N + 127) / 128, 1);  // Fout=128 / 64
  const int GW = (N * 32 + 255) / 256;  // gather: warp per row

  // L1: 256->256
  gemm_kernel<128, false><<<gA, 256>>>(x, W1, nullptr, bufA, N, 256, 256);
  gather_kernel<256><<<GW, 256>>>(bufA, bufB, N);

  // L2: 256->256  (b1 + lrelu fused into A-load)
  gemm_kernel<128, true><<<gA, 256>>>(bufB, W2, b1, bufA, N, 256, 256);
  gather_kernel<256><<<GW, 256>>>(bufA, bufB, N);

  // L3: 256->128
  gemm_kernel<128, true><<<gB, 256>>>(bufB, W3, b2, bufA, N, 256, 128);
  gather_kernel<128><<<GW, 256>>>(bufA, bufB, N);

  // L4: 128->64
  gemm_kernel<64, true><<<gB, 256>>>(bufB, W4, b3, bufA, N, 128, 64);
  gather_kernel<64><<<GW, 256>>>(bufA, bufB, N);

  // bias4 + lrelu + dropout + dense 64->10
  final_kernel<<<(N * 32 + 255) / 256, 256>>>(bufB, b4, W5, b5, (float*)d_out, N);
}

// round 8
// speedup vs baseline: 3.1891x; 1.3258x over previous
#include <cuda_runtime.h>
#include <stdint.h>

// ---------------------------------------------------------------------------
// ShallowGCNet: 4x GCNConv(lrelu) + dropout + dense
// N=50000 nodes, E=800000 edges, features 256->256->256->128->64->10
// GEMMs: 3xTF32 mma.sync (sm_80 base ISA -> compiles on plain sm_100).
// Aggregation: CSR gather (no float atomics).
// ---------------------------------------------------------------------------

__device__ float g_bufA[50000 * 256];
__device__ float g_bufB[50000 * 256];
__device__ float g_dinv[50000];
__device__ int   g_deg[50000];
__device__ int   g_off[50001];
__device__ int   g_bsum[64];
__device__ int   g_fill[50000];
__device__ int   g_csr_src[800000];
__device__ float g_csr_w[800000];
// tf32 hi/lo splits of W (same [K][Fout] layout), fp32-bit storage
__device__ float g_wtf_hi[172032];
__device__ float g_wtf_lo[172032];
// offsets: w1=0, w2=65536, w3=131072, w4=163840

// ------------------------------ degree ------------------------------------
__global__ void deg_init_kernel(int n) {
  int i = blockIdx.x * blockDim.x + threadIdx.x;
  if (i < n) { g_deg[i] = 0; g_fill[i] = 0; }
}
__global__ void deg_count_kernel(const int* __restrict__ dst, int E) {
  int e = blockIdx.x * blockDim.x + threadIdx.x;
  if (e < E) atomicAdd(&g_deg[dst[e]], 1);
}
__global__ void dinv_kernel(int n) {
  int i = blockIdx.x * blockDim.x + threadIdx.x;
  if (i < n) g_dinv[i] = 1.0f / sqrtf((float)(g_deg[i] + 1));
}

// ------------------------------ CSR build ----------------------------------
#define SCAN_BLK 1024
__global__ void scan1_kernel(int n) {
  __shared__ int sh[SCAN_BLK];
  int i = blockIdx.x * SCAN_BLK + threadIdx.x;
  int v = (i < n) ? g_deg[i] : 0;
  sh[threadIdx.x] = v;
  __syncthreads();
#pragma unroll
  for (int d = 1; d < SCAN_BLK; d <<= 1) {
    int t = (threadIdx.x >= d) ? sh[threadIdx.x - d] : 0;
    __syncthreads();
    sh[threadIdx.x] += t;
    __syncthreads();
  }
  if (i < n) g_off[i] = sh[threadIdx.x] - v;
  if (threadIdx.x == SCAN_BLK - 1) g_bsum[blockIdx.x] = sh[threadIdx.x];
}
__global__ void scan2_kernel(int nb) {
  __shared__ int sh[64];
  int v = (threadIdx.x < nb) ? g_bsum[threadIdx.x] : 0;
  sh[threadIdx.x] = v;
  __syncthreads();
#pragma unroll
  for (int d = 1; d < 64; d <<= 1) {
    int t = (threadIdx.x >= d) ? sh[threadIdx.x - d] : 0;
    __syncthreads();
    sh[threadIdx.x] += t;
    __syncthreads();
  }
  if (threadIdx.x < nb) g_bsum[threadIdx.x] = sh[threadIdx.x] - v;
}
__global__ void scan3_kernel(int n, int E) {
  int i = blockIdx.x * blockDim.x + threadIdx.x;
  if (i < n) g_off[i] += g_bsum[i >> 10];
  if (i == n) g_off[n] = E;
}
__global__ void fill_kernel(const int* __restrict__ src,
                            const int* __restrict__ dst, int E) {
  int e = blockIdx.x * blockDim.x + threadIdx.x;
  if (e >= E) return;
  int s = src[e], d = dst[e];
  int pos = g_off[d] + atomicAdd(&g_fill[d], 1);
  g_csr_src[pos] = s;
  g_csr_w[pos] = g_dinv[s];
}

// ------------------------- tf32 helpers ------------------------------------
__device__ __forceinline__ float2 tf32_split(float v) {
  uint32_t hu;
  asm("cvt.rna.tf32.f32 %0, %1;" : "=r"(hu) : "f"(v));
  float h = __uint_as_float(hu);
  float r = v - h;
  uint32_t lu;
  asm("cvt.rna.tf32.f32 %0, %1;" : "=r"(lu) : "f"(r));
  return make_float2(h, __uint_as_float(lu));
}

#define MMA_TF32(c, a, b)                                              \
  asm volatile(                                                        \
      "mma.sync.aligned.m16n8k8.row.col.f32.tf32.tf32.f32 "            \
      "{%0,%1,%2,%3}, {%4,%5,%6,%7}, {%8,%9}, {%0,%1,%2,%3};"          \
      : "+f"((c)[0]), "+f"((c)[1]), "+f"((c)[2]), "+f"((c)[3])         \
      : "r"((a)[0]), "r"((a)[1]), "r"((a)[2]), "r"((a)[3]),            \
        "r"((b)[0]), "r"((b)[1]))

// W -> tf32 hi/lo (once per call)
__global__ void split_w_kernel(const float* __restrict__ W,
                               float* __restrict__ hi,
                               float* __restrict__ lo, int n) {
  int i = blockIdx.x * blockDim.x + threadIdx.x;
  if (i >= n) return;
  float2 s = tf32_split(W[i]);
  hi[i] = s.x;
  lo[i] = s.y;
}

// ------------------------ 3xTF32 mma GEMM ----------------------------------
// C[:, col0:col0+BN] = act(A + preb) @ W.  BM=128, BK=32, 8 warps (4m x 2n),
// warp tile 32 x BN/2 in m16n8k8 atoms.  D = ah*wh + al*wh + ah*wl.
template<int BN, bool PRE>
__global__ void __launch_bounds__(256) gemm_tf32_kernel(
    const float* __restrict__ A, const float* __restrict__ Whi,
    const float* __restrict__ Wlo, const float* __restrict__ preb,
    float* __restrict__ C, int N, int K, int Fout) {
  constexpr int BM = 128, BK = 32;
  constexpr int AS = BK + 4;   // 36: (4g+t)%32 bijective -> conflict-free
  constexpr int BS = BN + 8;   // (8t+g)%32 bijective -> conflict-free
  constexpr int NA = BN / 16;  // n-atoms per warp (8 or 4)
  extern __shared__ float sm[];
  float* Ah = sm;                  // [BM][AS]
  float* Al = Ah + BM * AS;
  float* Bh = Al + BM * AS;        // [BK][BS]
  float* Bl = Bh + BK * BS;

  const int tid = threadIdx.x;
  const int wid = tid >> 5, lane = tid & 31;
  const int g = lane >> 2, t = lane & 3;
  const int wm = wid & 3, wn = wid >> 2;
  const int row0 = blockIdx.x * BM;
  const int col0 = blockIdx.y * BN;

  float c[2][NA][4];
#pragma unroll
  for (int ma = 0; ma < 2; ++ma)
#pragma unroll
    for (int na = 0; na < NA; ++na)
#pragma unroll
      for (int q = 0; q < 4; ++q) c[ma][na][q] = 0.f;

  for (int k0 = 0; k0 < K; k0 += BK) {
    // ---- A tile: 128x32 fp32 -> split -> smem ----
#pragma unroll
    for (int p = 0; p < 4; ++p) {
      int idx = tid + p * 256;          // 1024 float4
      int r = idx >> 3, kq = idx & 7;
      int grow = row0 + r;
      float4 v = make_float4(0.f, 0.f, 0.f, 0.f);
      if (grow < N) v = *(const float4*)(A + (size_t)grow * K + k0 + kq * 4);
      if (PRE) {
        float4 b = *(const float4*)(preb + k0 + kq * 4);
        v.x += b.x; v.y += b.y; v.z += b.z; v.w += b.w;
        v.x = v.x > 0.f ? v.x : 0.01f * v.x;
        v.y = v.y > 0.f ? v.y : 0.01f * v.y;
        v.z = v.z > 0.f ? v.z : 0.01f * v.z;
        v.w = v.w > 0.f ? v.w : 0.01f * v.w;
      }
      float2 sx = tf32_split(v.x), sy = tf32_split(v.y);
      float2 sz = tf32_split(v.z), sw = tf32_split(v.w);
      float* ph = Ah + r * AS + kq * 4;
      float* pl = Al + r * AS + kq * 4;
      ph[0] = sx.x; ph[1] = sy.x; ph[2] = sz.x; ph[3] = sw.x;
      pl[0] = sx.y; pl[1] = sy.y; pl[2] = sz.y; pl[3] = sw.y;
    }
    // ---- B tile: BKxBN (pre-split) -> smem ----
#pragma unroll
    for (int p = 0; p < (BK * BN / 4 + 255) / 256; ++p) {
      int idx = tid + p * 256;
      if (idx < BK * BN / 4) {
        int r = idx / (BN / 4), cq = idx % (BN / 4);
        const float* gh = Whi + (size_t)(k0 + r) * Fout + col0 + cq * 4;
        const float* gl = Wlo + (size_t)(k0 + r) * Fout + col0 + cq * 4;
        *(float4*)(Bh + r * BS + cq * 4) = *(const float4*)gh;
        *(float4*)(Bl + r * BS + cq * 4) = *(const float4*)gl;
      }
    }
    __syncthreads();

#pragma unroll
    for (int ka = 0; ka < BK / 8; ++ka) {
      uint32_t ah[2][4], al[2][4];
#pragma unroll
      for (int ma = 0; ma < 2; ++ma) {
        int r = wm * 32 + ma * 16;
        const float* p0 = Ah + (r + g) * AS + ka * 8 + t;
        const float* p1 = Ah + (r + g + 8) * AS + ka * 8 + t;
        ah[ma][0] = __float_as_uint(p0[0]);
        ah[ma][1] = __float_as_uint(p1[0]);
        ah[ma][2] = __float_as_uint(p0[4]);
        ah[ma][3] = __float_as_uint(p1[4]);
        const float* q0 = Al + (r + g) * AS + ka * 8 + t;
        const float* q1 = Al + (r + g + 8) * AS + ka * 8 + t;
        al[ma][0] = __float_as_uint(q0[0]);
        al[ma][1] = __float_as_uint(q1[0]);
        al[ma][2] = __float_as_uint(q0[4]);
        al[ma][3] = __float_as_uint(q1[4]);
      }
      uint32_t bh[NA][2], bl[NA][2];
#pragma unroll
      for (int na = 0; na < NA; ++na) {
        int cc = wn * (BN / 2) + na * 8 + g;
        bh[na][0] = __float_as_uint(Bh[(ka * 8 + t) * BS + cc]);
        bh[na][1] = __float_as_uint(Bh[(ka * 8 + t + 4) * BS + cc]);
        bl[na][0] = __float_as_uint(Bl[(ka * 8 + t) * BS + cc]);
        bl[na][1] = __float_as_uint(Bl[(ka * 8 + t + 4) * BS + cc]);
      }
#pragma unroll
      for (int ma = 0; ma < 2; ++ma)
#pragma unroll
        for (int na = 0; na < NA; ++na) {
          MMA_TF32(c[ma][na], ah[ma], bh[na]);
          MMA_TF32(c[ma][na], al[ma], bh[na]);
          MMA_TF32(c[ma][na], ah[ma], bl[na]);
        }
    }
    __syncthreads();
  }

  // ---- epilogue ----
#pragma unroll
  for (int ma = 0; ma < 2; ++ma) {
    int row = row0 + wm * 32 + ma * 16 + g;
#pragma unroll
    for (int na = 0; na < NA; ++na) {
      int col = col0 + wn * (BN / 2) + na * 8 + t * 2;
      if (row < N)
        *(float2*)(C + (size_t)row * Fout + col) =
            make_float2(c[ma][na][0], c[ma][na][1]);
      if (row + 8 < N)
        *(float2*)(C + (size_t)(row + 8) * Fout + col) =
            make_float2(c[ma][na][2], c[ma][na][3]);
    }
  }
}

// ----------------------- CSR gather aggregation -----------------------------
template<int F>
__global__ void gather_kernel(const float* __restrict__ tmp,
                              float* __restrict__ out, int n) {
  int w = (blockIdx.x * blockDim.x + threadIdx.x) >> 5;
  int lane = threadIdx.x & 31;
  if (w >= n) return;
  int beg = g_off[w], end = g_off[w + 1];
  float dr = g_dinv[w];

  if constexpr (F >= 128) {
    constexpr int NV = F / 128;
    float4 acc[NV];
    const float4* self = (const float4*)(tmp + (size_t)w * F);
#pragma unroll
    for (int v = 0; v < NV; ++v) {
      float4 x = self[lane + 32 * v];
      acc[v] = make_float4(x.x * dr, x.y * dr, x.z * dr, x.w * dr);
    }
    for (int e0 = beg; e0 < end; e0 += 32) {
      int ne = min(32, end - e0);
      int s = 0; float ww = 0.f;
      if (lane < ne) { s = g_csr_src[e0 + lane]; ww = g_csr_w[e0 + lane]; }
      for (int j = 0; j < ne; ++j) {
        int sj = __shfl_sync(0xffffffffu, s, j);
        float wj = __shfl_sync(0xffffffffu, ww, j);
        const float4* sr = (const float4*)(tmp + (size_t)sj * F);
#pragma unroll
        for (int v = 0; v < NV; ++v) {
          float4 x = sr[lane + 32 * v];
          acc[v].x += wj * x.x; acc[v].y += wj * x.y;
          acc[v].z += wj * x.z; acc[v].w += wj * x.w;
        }
      }
    }
    float4* orow = (float4*)(out + (size_t)w * F);
#pragma unroll
    for (int v = 0; v < NV; ++v)
      orow[lane + 32 * v] = make_float4(acc[v].x * dr, acc[v].y * dr,
                                        acc[v].z * dr, acc[v].w * dr);
  } else {
    float2 acc;
    const float2* self = (const float2*)(tmp + (size_t)w * F);
    {
      float2 x = self[lane];
      acc = make_float2(x.x * dr, x.y * dr);
    }
    for (int e0 = beg; e0 < end; e0 += 32) {
      int ne = min(32, end - e0);
      int s = 0; float ww = 0.f;
      if (lane < ne) { s = g_csr_src[e0 + lane]; ww = g_csr_w[e0 + lane]; }
      for (int j = 0; j < ne; ++j) {
        int sj = __shfl_sync(0xffffffffu, s, j);
        float wj = __shfl_sync(0xffffffffu, ww, j);
        float2 x = ((const float2*)(tmp + (size_t)sj * F))[lane];
        acc.x += wj * x.x; acc.y += wj * x.y;
      }
    }
    ((float2*)(out + (size_t)w * F))[lane] =
        make_float2(acc.x * dr, acc.y * dr);
  }
}

// ------------------- dropout (JAX threefry) + dense -------------------------
#define TF_ROUND(x0, x1, r)                         \
  { x0 += x1; x1 = (x1 << (r)) | (x1 >> (32 - (r))); x1 ^= x0; }

__device__ __forceinline__ uint32_t threefry_bits(uint32_t idx) {
  const uint32_t k0 = 0u, k1 = 42u;
  const uint32_t k2 = 0x1BD11BDAu ^ k0 ^ k1;
  uint32_t x0 = 0u, x1 = idx;
  x0 += k0; x1 += k1;
  TF_ROUND(x0, x1, 13) TF_ROUND(x0, x1, 15) TF_ROUND(x0, x1, 26) TF_ROUND(x0, x1, 6)
  x0 += k1; x1 += k2 + 1u;
  TF_ROUND(x0, x1, 17) TF_ROUND(x0, x1, 29) TF_ROUND(x0, x1, 16) TF_ROUND(x0, x1, 24)
  x0 += k2; x1 += k0 + 2u;
  TF_ROUND(x0, x1, 13) TF_ROUND(x0, x1, 15) TF_ROUND(x0, x1, 26) TF_ROUND(x0, x1, 6)
  x0 += k0; x1 += k1 + 3u;
  TF_ROUND(x0, x1, 17) TF_ROUND(x0, x1, 29) TF_ROUND(x0, x1, 16) TF_ROUND(x0, x1, 24)
  x0 += k1; x1 += k2 + 4u;
  TF_ROUND(x0, x1, 13) TF_ROUND(x0, x1, 15) TF_ROUND(x0, x1, 26) TF_ROUND(x0, x1, 6)
  x0 += k2; x1 += k0 + 5u;
  return x0 ^ x1;
}

__global__ void final_kernel(const float* __restrict__ h,
                             const float* __restrict__ b4,
                             const float* __restrict__ W5,
                             const float* __restrict__ b5,
                             float* __restrict__ out, int n) {
  __shared__ float w5s[640];
  __shared__ float b5s[16];
  for (int i = threadIdx.x; i < 640; i += blockDim.x) w5s[i] = W5[i];
  if (threadIdx.x < 10) b5s[threadIdx.x] = b5[threadIdx.x];
  __syncthreads();
  int gw = (blockIdx.x * blockDim.x + threadIdx.x) >> 5;
  int lane = threadIdx.x & 31;
  if (gw >= n) return;
  int i = gw;
  float v0 = h[i * 64 + lane] + b4[lane];
  v0 = (v0 > 0.f) ? v0 : 0.01f * v0;
  float v1 = h[i * 64 + lane + 32] + b4[lane + 32];
  v1 = (v1 > 0.f) ? v1 : 0.01f * v1;
  uint32_t bits0 = threefry_bits((uint32_t)(i * 64 + lane));
  uint32_t bits1 = threefry_bits((uint32_t)(i * 64 + lane + 32));
  v0 = (bits0 & 0x80000000u) ? 0.f : v0 * 2.f;
  v1 = (bits1 & 0x80000000u) ? 0.f : v1 * 2.f;
#pragma unroll
  for (int j = 0; j < 10; ++j) {
    float p = v0 * w5s[lane * 10 + j] + v1 * w5s[(lane + 32) * 10 + j];
#pragma unroll
    for (int off = 16; off; off >>= 1)
      p += __shfl_xor_sync(0xffffffffu, p, off);
    if (lane == 0) out[i * 10 + j] = p + b5s[j];
  }
}

// ------------------------------ launch -------------------------------------
extern "C" void kernel_launch(void* const* d_in, const int* in_sizes, int n_in,
                              void* d_out, int out_size) {
  const float* x = (const float*)d_in[0];
  const int* ei = (const int*)d_in[1];   // int32
  const float* W1 = (const float*)d_in[2];
  const float* b1 = (const float*)d_in[3];
  const float* W2 = (const float*)d_in[4];
  const float* b2 = (const float*)d_in[5];
  const float* W3 = (const float*)d_in[6];
  const float* b3 = (const float*)d_in[7];
  const float* W4 = (const float*)d_in[8];
  const float* b4 = (const float*)d_in[9];
  const float* W5 = (const float*)d_in[10];
  const float* b5 = (const float*)d_in[11];
  const int N = in_sizes[0] / 256;
  const int E = in_sizes[1] / 2;
  const int* src = ei;
  const int* dstp = ei + E;

  float* bufA = nullptr;
  float* bufB = nullptr;
  float* whi = nullptr;
  float* wlo = nullptr;
  cudaGetSymbolAddress((void**)&bufA, g_bufA);
  cudaGetSymbolAddress((void**)&bufB, g_bufB);
  cudaGetSymbolAddress((void**)&whi, g_wtf_hi);
  cudaGetSymbolAddress((void**)&wlo, g_wtf_lo);

  // dynamic smem sizes
  constexpr int SM_128 = (128 * 36 * 2 + 32 * 136 * 2) * 4;  // 71680
  constexpr int SM_64  = (128 * 36 * 2 + 32 * 72 * 2) * 4;   // 55296
  cudaFuncSetAttribute(gemm_tf32_kernel<128, false>,
                       cudaFuncAttributeMaxDynamicSharedMemorySize, SM_128);
  cudaFuncSetAttribute(gemm_tf32_kernel<128, true>,
                       cudaFuncAttributeMaxDynamicSharedMemorySize, SM_128);
  cudaFuncSetAttribute(gemm_tf32_kernel<64, true>,
                       cudaFuncAttributeMaxDynamicSharedMemorySize, SM_64);

  // W tf32 splits (once per call)
  split_w_kernel<<<(65536 + 255) / 256, 256>>>(W1, whi, wlo, 65536);
  split_w_kernel<<<(65536 + 255) / 256, 256>>>(W2, whi + 65536, wlo + 65536, 65536);
  split_w_kernel<<<(32768 + 255) / 256, 256>>>(W3, whi + 131072, wlo + 131072, 32768);
  split_w_kernel<<<(8192 + 255) / 256, 256>>>(W4, whi + 163840, wlo + 163840, 8192);

  // ---- normalization + CSR build ----
  deg_init_kernel<<<(N + 255) / 256, 256>>>(N);
  deg_count_kernel<<<(E + 255) / 256, 256>>>(dstp, E);
  dinv_kernel<<<(N + 255) / 256, 256>>>(N);
  int nblk = (N + SCAN_BLK - 1) / SCAN_BLK;
  scan1_kernel<<<nblk, SCAN_BLK>>>(N);
  scan2_kernel<<<1, 64>>>(nblk);
  scan3_kernel<<<(N + 256) / 256, 256>>>(N, E);
  fill_kernel<<<(E + 255) / 256, 256>>>(src, dstp, E);

  const int MB = (N + 127) / 128;       // 391
  const int GW = (N * 32 + 255) / 256;  // gather: warp per row

  // L1: 256->256
  gemm_tf32_kernel<128, false><<<dim3(MB, 2), 256, SM_128>>>(
      x, whi, wlo, nullptr, bufA, N, 256, 256);
  gather_kernel<256><<<GW, 256>>>(bufA, bufB, N);

  // L2: 256->256  (b1 + lrelu fused)
  gemm_tf32_kernel<128, true><<<dim3(MB, 2), 256, SM_128>>>(
      bufB, whi + 65536, wlo + 65536, b1, bufA, N, 256, 256);
  gather_kernel<256><<<GW, 256>>>(bufA, bufB, N);

  // L3: 256->128
  gemm_tf32_kernel<128, true><<<dim3(MB, 1), 256, SM_128>>>(
      bufB, whi + 131072, wlo + 131072, b2, bufA, N, 256, 128);
  gather_kernel<128><<<GW, 256>>>(bufA, bufB, N);

  // L4: 128->64
  gemm_tf32_kernel<64, true><<<dim3(MB, 1), 256, SM_64>>>(
      bufB, whi + 163840, wlo + 163840, b3, bufA, N, 128, 64);
  gather_kernel<64><<<GW, 256>>>(bufA, bufB, N);

  // bias4 + lrelu + dropout + dense 64->10
  final_kernel<<<(N * 32 + 255) / 256, 256>>>(bufB, b4, W5, b5, (float*)d_out, N);
}

// round 9
// speedup vs baseline: 3.8000x; 1.1916x over previous
#include <cuda_runtime.h>
#include <cuda_bf16.h>
#include <stdint.h>

// ---------------------------------------------------------------------------
// ShallowGCNet: 4x GCNConv(lrelu) + dropout + dense
// N=50000, E=800000, features 256->256->256->128->64->10
// GEMM: bf16 double-split (3 products) m16n8k16 mma.sync, cp.async 2-stage.
// Aggregation: CSR gather with fused bias+lrelu+bf16-split epilogue.
// ---------------------------------------------------------------------------

__device__ float g_tmp[50000 * 256];   // GEMM output / gather input
__device__ float g_y[50000 * 64];      // L4 gather output (raw)
__device__ __nv_bfloat16 g_ah[50000 * 256];  // A hi plane
__device__ __nv_bfloat16 g_al[50000 * 256];  // A lo plane
__device__ __nv_bfloat16 g_wh[172032];       // W^T hi  [Fout][K]
__device__ __nv_bfloat16 g_wl[172032];       // W^T lo
// offsets: w1=0 w2=65536 w3=131072 w4=163840
__device__ float g_dinv[50000];
__device__ int   g_deg[50000];
__device__ int   g_off[50001];
__device__ int   g_bsum[64];
__device__ int   g_fill[50000];
__device__ int   g_csr_src[800000];
__device__ float g_csr_w[800000];

// ------------------------------ degree ------------------------------------
__global__ void deg_init_kernel(int n) {
  int i = blockIdx.x * blockDim.x + threadIdx.x;
  if (i < n) { g_deg[i] = 0; g_fill[i] = 0; }
}
__global__ void deg_count_kernel(const int* __restrict__ dst, int E) {
  int e = blockIdx.x * blockDim.x + threadIdx.x;
  if (e < E) atomicAdd(&g_deg[dst[e]], 1);
}
__global__ void dinv_kernel(int n) {
  int i = blockIdx.x * blockDim.x + threadIdx.x;
  if (i < n) g_dinv[i] = 1.0f / sqrtf((float)(g_deg[i] + 1));
}

// ------------------------------ CSR build ----------------------------------
#define SCAN_BLK 1024
__global__ void scan1_kernel(int n) {
  __shared__ int sh[SCAN_BLK];
  int i = blockIdx.x * SCAN_BLK + threadIdx.x;
  int v = (i < n) ? g_deg[i] : 0;
  sh[threadIdx.x] = v;
  __syncthreads();
#pragma unroll
  for (int d = 1; d < SCAN_BLK; d <<= 1) {
    int t = (threadIdx.x >= d) ? sh[threadIdx.x - d] : 0;
    __syncthreads();
    sh[threadIdx.x] += t;
    __syncthreads();
  }
  if (i < n) g_off[i] = sh[threadIdx.x] - v;
  if (threadIdx.x == SCAN_BLK - 1) g_bsum[blockIdx.x] = sh[threadIdx.x];
}
__global__ void scan2_kernel(int nb) {
  __shared__ int sh[64];
  int v = (threadIdx.x < nb) ? g_bsum[threadIdx.x] : 0;
  sh[threadIdx.x] = v;
  __syncthreads();
#pragma unroll
  for (int d = 1; d < 64; d <<= 1) {
    int t = (threadIdx.x >= d) ? sh[threadIdx.x - d] : 0;
    __syncthreads();
    sh[threadIdx.x] += t;
    __syncthreads();
  }
  if (threadIdx.x < nb) g_bsum[threadIdx.x] = sh[threadIdx.x] - v;
}
__global__ void scan3_kernel(int n, int E) {
  int i = blockIdx.x * blockDim.x + threadIdx.x;
  if (i < n) g_off[i] += g_bsum[i >> 10];
  if (i == n) g_off[n] = E;
}
__global__ void fill_kernel(const int* __restrict__ src,
                            const int* __restrict__ dst, int E) {
  int e = blockIdx.x * blockDim.x + threadIdx.x;
  if (e >= E) return;
  int s = src[e], d = dst[e];
  int pos = g_off[d] + atomicAdd(&g_fill[d], 1);
  g_csr_src[pos] = s;
  g_csr_w[pos] = g_dinv[s];
}

// ------------------------- bf16 split helpers -------------------------------
__device__ __forceinline__ uint32_t pack_bf2(__nv_bfloat16 a, __nv_bfloat16 b) {
  return (uint32_t)__bfloat16_as_ushort(a) |
         ((uint32_t)__bfloat16_as_ushort(b) << 16);
}

// x -> hi/lo planes (layer-1 A, no activation)
__global__ void split_x_kernel(const float* __restrict__ x,
                               __nv_bfloat16* __restrict__ h,
                               __nv_bfloat16* __restrict__ l, int n) {
  int i = blockIdx.x * blockDim.x + threadIdx.x;
  if (i >= n) return;
  float v = x[i];
  __nv_bfloat16 hh = __float2bfloat16(v);
  h[i] = hh;
  l[i] = __float2bfloat16(v - __bfloat162float(hh));
}

// W [K][Fout] -> transposed hi/lo planes [Fout][K]
__global__ void split_wt_kernel(const float* __restrict__ W,
                                __nv_bfloat16* __restrict__ h,
                                __nv_bfloat16* __restrict__ l,
                                int K, int Fout) {
  int i = blockIdx.x * blockDim.x + threadIdx.x;
  if (i >= K * Fout) return;
  int k = i / Fout, nn = i % Fout;
  float v = W[i];
  __nv_bfloat16 hh = __float2bfloat16(v);
  h[nn * K + k] = hh;
  l[nn * K + k] = __float2bfloat16(v - __bfloat162float(hh));
}

// ------------------------ bf16 mma GEMM ------------------------------------
__device__ __forceinline__ void cp16(uint32_t dst, const void* src) {
  asm volatile("cp.async.ca.shared.global [%0], [%1], 16;"
               :: "r"(dst), "l"(src));
}
__device__ __forceinline__ void cp_commit() {
  asm volatile("cp.async.commit_group;");
}
template<int n> __device__ __forceinline__ void cp_wait() {
  asm volatile("cp.async.wait_group %0;" :: "n"(n));
}

#define MMA_BF16(c, a, b)                                              \
  asm volatile(                                                        \
      "mma.sync.aligned.m16n8k16.row.col.f32.bf16.bf16.f32 "           \
      "{%0,%1,%2,%3}, {%4,%5,%6,%7}, {%8,%9}, {%0,%1,%2,%3};"          \
      : "+f"((c)[0]), "+f"((c)[1]), "+f"((c)[2]), "+f"((c)[3])         \
      : "r"((a)[0]), "r"((a)[1]), "r"((a)[2]), "r"((a)[3]),            \
        "r"((b)[0]), "r"((b)[1]))

// C[:, col0:col0+BN] = (Ah+Al) @ (Bh+Bl)^T   (3-product bf16 split)
// A planes [N][K] k-major, B planes [Fout][K] k-major. BM=128, BK=32,
// 8 warps 4m x 2n; per-warp 32 x BN/2.  Smem stride 80B (conflict-free).
template<int BN>
__global__ void __launch_bounds__(256, 1) gemm_bf16_kernel(
    const __nv_bfloat16* __restrict__ Ah, const __nv_bfloat16* __restrict__ Al,
    const __nv_bfloat16* __restrict__ Bh, const __nv_bfloat16* __restrict__ Bl,
    float* __restrict__ C, int N, int K, int Fout) {
  constexpr int SB = BN * 80;            // one B plane per stage (bytes)
  constexpr int ST = 20480 + 2 * SB;     // stage size (A 2x10240 + B 2xSB)
  constexpr int NA = BN / 16;            // n-atoms per warp
  extern __shared__ char smc[];
  const uint32_t smu = (uint32_t)__cvta_generic_to_shared(smc);

  const int tid = threadIdx.x;
  const int wid = tid >> 5, lane = tid & 31;
  const int g = lane >> 2, t = lane & 3;
  const int wm = wid & 3, wn = wid >> 2;
  const int row0 = blockIdx.x * 128;
  const int col0 = blockIdx.y * BN;
  const int NIT = K >> 5;

  float c[2][NA][4] = {};

  auto load_stage = [&](int s, int k0) {
    uint32_t sb = smu + (uint32_t)s * ST;
    int r = tid >> 2, q = tid & 3;
#pragma unroll
    for (int p = 0; p < 2; ++p) {               // A: 128 rows
      int rr = r + p * 64;
      int grow = row0 + rr; if (grow >= N) grow = N - 1;  // clamp: rows>=N unused
      const __nv_bfloat16* sa = Ah + (size_t)grow * K + k0 + q * 8;
      const __nv_bfloat16* sl = Al + (size_t)grow * K + k0 + q * 8;
      cp16(sb + rr * 80 + q * 16, sa);
      cp16(sb + 10240 + rr * 80 + q * 16, sl);
    }
#pragma unroll
    for (int p = 0; p < BN / 64; ++p) {         // B: BN rows
      int rr = r + p * 64;
      int gc = col0 + rr;
      cp16(sb + 20480 + rr * 80 + q * 16, Bh + (size_t)gc * K + k0 + q * 8);
      cp16(sb + 20480 + SB + rr * 80 + q * 16, Bl + (size_t)gc * K + k0 + q * 8);
    }
  };

  load_stage(0, 0);
  cp_commit();
  for (int it = 0; it < NIT; ++it) {
    if (it + 1 < NIT) {
      load_stage((it + 1) & 1, (it + 1) * 32);
      cp_commit();
      cp_wait<1>();
    } else {
      cp_wait<0>();
    }
    __syncthreads();
    char* sb = smc + (it & 1) * ST;
#pragma unroll
    for (int ka = 0; ka < 2; ++ka) {
      uint32_t ah[2][4], al[2][4];
#pragma unroll
      for (int ma = 0; ma < 2; ++ma) {
        char* p = sb + (wm * 32 + ma * 16 + g) * 80 + ka * 32 + 4 * t;
        ah[ma][0] = *(uint32_t*)p;
        ah[ma][1] = *(uint32_t*)(p + 640);
        ah[ma][2] = *(uint32_t*)(p + 16);
        ah[ma][3] = *(uint32_t*)(p + 656);
        char* pq = p + 10240;
        al[ma][0] = *(uint32_t*)pq;
        al[ma][1] = *(uint32_t*)(pq + 640);
        al[ma][2] = *(uint32_t*)(pq + 16);
        al[ma][3] = *(uint32_t*)(pq + 656);
      }
      uint32_t bh[NA][2], bl[NA][2];
#pragma unroll
      for (int na = 0; na < NA; ++na) {
        char* p = sb + 20480 + (wn * (BN / 2) + na * 8 + g) * 80 + ka * 32 + 4 * t;
        bh[na][0] = *(uint32_t*)p;
        bh[na][1] = *(uint32_t*)(p + 16);
        bl[na][0] = *(uint32_t*)(p + SB);
        bl[na][1] = *(uint32_t*)(p + SB + 16);
      }
#pragma unroll
      for (int ma = 0; ma < 2; ++ma)
#pragma unroll
        for (int na = 0; na < NA; ++na) {
          MMA_BF16(c[ma][na], ah[ma], bh[na]);
          MMA_BF16(c[ma][na], al[ma], bh[na]);
          MMA_BF16(c[ma][na], ah[ma], bl[na]);
        }
    }
    __syncthreads();
  }

#pragma unroll
  for (int ma = 0; ma < 2; ++ma) {
    int row = row0 + wm * 32 + ma * 16 + g;
#pragma unroll
    for (int na = 0; na < NA; ++na) {
      int col = col0 + wn * (BN / 2) + na * 8 + t * 2;
      if (row < N)
        *(float2*)(C + (size_t)row * Fout + col) =
            make_float2(c[ma][na][0], c[ma][na][1]);
      if (row + 8 < N)
        *(float2*)(C + (size_t)(row + 8) * Fout + col) =
            make_float2(c[ma][na][2], c[ma][na][3]);
    }
  }
}

// -------------- CSR gather + fused bias/lrelu/bf16-split --------------------
// z = lrelu( dinv[d]*(dinv[d]*h[d] + sum dinv[s]*h[s]) + bias ); write hi/lo.
template<int F>
__global__ void gather_split_kernel(const float* __restrict__ tmp,
                                    const float* __restrict__ bias,
                                    __nv_bfloat16* __restrict__ oh,
                                    __nv_bfloat16* __restrict__ ol, int n) {
  int w = (blockIdx.x * blockDim.x + threadIdx.x) >> 5;
  int lane = threadIdx.x & 31;
  if (w >= n) return;
  int beg = g_off[w], end = g_off[w + 1];
  float dr = g_dinv[w];
  constexpr int NV = F / 128;
  float4 acc[NV];
  const float4* self = (const float4*)(tmp + (size_t)w * F);
#pragma unroll
  for (int v = 0; v < NV; ++v) {
    float4 x = self[lane + 32 * v];
    acc[v] = make_float4(x.x * dr, x.y * dr, x.z * dr, x.w * dr);
  }
  for (int e0 = beg; e0 < end; e0 += 32) {
    int ne = min(32, end - e0);
    int s = 0; float ww = 0.f;
    if (lane < ne) { s = g_csr_src[e0 + lane]; ww = g_csr_w[e0 + lane]; }
    for (int j = 0; j < ne; ++j) {
      int sj = __shfl_sync(0xffffffffu, s, j);
      float wj = __shfl_sync(0xffffffffu, ww, j);
      const float4* sr = (const float4*)(tmp + (size_t)sj * F);
#pragma unroll
      for (int v = 0; v < NV; ++v) {
        float4 x = sr[lane + 32 * v];
        acc[v].x += wj * x.x; acc[v].y += wj * x.y;
        acc[v].z += wj * x.z; acc[v].w += wj * x.w;
      }
    }
  }
  uint32_t* ph = (uint32_t*)(oh + (size_t)w * F);
  uint32_t* pl = (uint32_t*)(ol + (size_t)w * F);
#pragma unroll
  for (int v = 0; v < NV; ++v) {
    int cb = lane + 32 * v;
    float4 b = *(const float4*)(bias + 4 * cb);
    float4 z = make_float4(acc[v].x * dr + b.x, acc[v].y * dr + b.y,
                           acc[v].z * dr + b.z, acc[v].w * dr + b.w);
    z.x = z.x > 0.f ? z.x : 0.01f * z.x;
    z.y = z.y > 0.f ? z.y : 0.01f * z.y;
    z.z = z.z > 0.f ? z.z : 0.01f * z.z;
    z.w = z.w > 0.f ? z.w : 0.01f * z.w;
    __nv_bfloat16 hx = __float2bfloat16(z.x), hy = __float2bfloat16(z.y);
    __nv_bfloat16 hz = __float2bfloat16(z.z), hw = __float2bfloat16(z.w);
    ph[2 * cb + 0] = pack_bf2(hx, hy);
    ph[2 * cb + 1] = pack_bf2(hz, hw);
    pl[2 * cb + 0] = pack_bf2(__float2bfloat16(z.x - __bfloat162float(hx)),
                              __float2bfloat16(z.y - __bfloat162float(hy)));
    pl[2 * cb + 1] = pack_bf2(__float2bfloat16(z.z - __bfloat162float(hz)),
                              __float2bfloat16(z.w - __bfloat162float(hw)));
  }
}

// Raw gather for the last layer (F=64): final_kernel applies b4+lrelu itself.
__global__ void gather_raw64_kernel(const float* __restrict__ tmp,
                                    float* __restrict__ out, int n) {
  int w = (blockIdx.x * blockDim.x + threadIdx.x) >> 5;
  int lane = threadIdx.x & 31;
  if (w >= n) return;
  int beg = g_off[w], end = g_off[w + 1];
  float dr = g_dinv[w];
  float2 acc;
  {
    float2 x = ((const float2*)(tmp + (size_t)w * 64))[lane];
    acc = make_float2(x.x * dr, x.y * dr);
  }
  for (int e0 = beg; e0 < end; e0 += 32) {
    int ne = min(32, end - e0);
    int s = 0; float ww = 0.f;
    if (lane < ne) { s = g_csr_src[e0 + lane]; ww = g_csr_w[e0 + lane]; }
    for (int j = 0; j < ne; ++j) {
      int sj = __shfl_sync(0xffffffffu, s, j);
      float wj = __shfl_sync(0xffffffffu, ww, j);
      float2 x = ((const float2*)(tmp + (size_t)sj * 64))[lane];
      acc.x += wj * x.x; acc.y += wj * x.y;
    }
  }
  ((float2*)(out + (size_t)w * 64))[lane] = make_float2(acc.x * dr, acc.y * dr);
}

// ------------------- dropout (JAX threefry) + dense -------------------------
#define TF_ROUND(x0, x1, r)                         \
  { x0 += x1; x1 = (x1 << (r)) | (x1 >> (32 - (r))); x1 ^= x0; }

__device__ __forceinline__ uint32_t threefry_bits(uint32_t idx) {
  const uint32_t k0 = 0u, k1 = 42u;
  const uint32_t k2 = 0x1BD11BDAu ^ k0 ^ k1;
  uint32_t x0 = 0u, x1 = idx;
  x0 += k0; x1 += k1;
  TF_ROUND(x0, x1, 13) TF_ROUND(x0, x1, 15) TF_ROUND(x0, x1, 26) TF_ROUND(x0, x1, 6)
  x0 += k1; x1 += k2 + 1u;
  TF_ROUND(x0, x1, 17) TF_ROUND(x0, x1, 29) TF_ROUND(x0, x1, 16) TF_ROUND(x0, x1, 24)
  x0 += k2; x1 += k0 + 2u;
  TF_ROUND(x0, x1, 13) TF_ROUND(x0, x1, 15) TF_ROUND(x0, x1, 26) TF_ROUND(x0, x1, 6)
  x0 += k0; x1 += k1 + 3u;
  TF_ROUND(x0, x1, 17) TF_ROUND(x0, x1, 29) TF_ROUND(x0, x1, 16) TF_ROUND(x0, x1, 24)
  x0 += k1; x1 += k2 + 4u;
  TF_ROUND(x0, x1, 13) TF_ROUND(x0, x1, 15) TF_ROUND(x0, x1, 26) TF_ROUND(x0, x1, 6)
  x0 += k2; x1 += k0 + 5u;
  return x0 ^ x1;
}

__global__ void final_kernel(const float* __restrict__ h,
                             const float* __restrict__ b4,
                             const float* __restrict__ W5,
                             const float* __restrict__ b5,
                             float* __restrict__ out, int n) {
  __shared__ float w5s[640];
  __shared__ float b5s[16];
  for (int i = threadIdx.x; i < 640; i += blockDim.x) w5s[i] = W5[i];
  if (threadIdx.x < 10) b5s[threadIdx.x] = b5[threadIdx.x];
  __syncthreads();
  int gw = (blockIdx.x * blockDim.x + threadIdx.x) >> 5;
  int lane = threadIdx.x & 31;
  if (gw >= n) return;
  int i = gw;
  float v0 = h[i * 64 + lane] + b4[lane];
  v0 = (v0 > 0.f) ? v0 : 0.01f * v0;
  float v1 = h[i * 64 + lane + 32] + b4[lane + 32];
  v1 = (v1 > 0.f) ? v1 : 0.01f * v1;
  uint32_t bits0 = threefry_bits((uint32_t)(i * 64 + lane));
  uint32_t bits1 = threefry_bits((uint32_t)(i * 64 + lane + 32));
  v0 = (bits0 & 0x80000000u) ? 0.f : v0 * 2.f;
  v1 = (bits1 & 0x80000000u) ? 0.f : v1 * 2.f;
#pragma unroll
  for (int j = 0; j < 10; ++j) {
    float p = v0 * w5s[lane * 10 + j] + v1 * w5s[(lane + 32) * 10 + j];
#pragma unroll
    for (int off = 16; off; off >>= 1)
      p += __shfl_xor_sync(0xffffffffu, p, off);
    if (lane == 0) out[i * 10 + j] = p + b5s[j];
  }
}

// ------------------------------ launch -------------------------------------
extern "C" void kernel_launch(void* const* d_in, const int* in_sizes, int n_in,
                              void* d_out, int out_size) {
  const float* x = (const float*)d_in[0];
  const int* ei = (const int*)d_in[1];   // int32
  const float* W1 = (const float*)d_in[2];
  const float* b1 = (const float*)d_in[3];
  const float* W2 = (const float*)d_in[4];
  const float* b2 = (const float*)d_in[5];
  const float* W3 = (const float*)d_in[6];
  const float* b3 = (const float*)d_in[7];
  const float* W4 = (const float*)d_in[8];
  const float* b4 = (const float*)d_in[9];
  const float* W5 = (const float*)d_in[10];
  const float* b5 = (const float*)d_in[11];
  const int N = in_sizes[0] / 256;
  const int E = in_sizes[1] / 2;
  const int* src = ei;
  const int* dstp = ei + E;

  float* tmp = nullptr; float* y = nullptr;
  __nv_bfloat16 *ah = nullptr, *al = nullptr, *wh = nullptr, *wl = nullptr;
  cudaGetSymbolAddress((void**)&tmp, g_tmp);
  cudaGetSymbolAddress((void**)&y, g_y);
  cudaGetSymbolAddress((void**)&ah, g_ah);
  cudaGetSymbolAddress((void**)&al, g_al);
  cudaGetSymbolAddress((void**)&wh, g_wh);
  cudaGetSymbolAddress((void**)&wl, g_wl);

  constexpr int SM_128 = 2 * (20480 + 2 * 128 * 80);  // 81920
  constexpr int SM_64  = 2 * (20480 + 2 * 64 * 80);   // 61440
  cudaFuncSetAttribute(gemm_bf16_kernel<128>,
                       cudaFuncAttributeMaxDynamicSharedMemorySize, SM_128);
  cudaFuncSetAttribute(gemm_bf16_kernel<64>,
                       cudaFuncAttributeMaxDynamicSharedMemorySize, SM_64);

  // operand splits
  split_x_kernel<<<(N * 256 + 255) / 256, 256>>>(x, ah, al, N * 256);
  split_wt_kernel<<<(65536 + 255) / 256, 256>>>(W1, wh, wl, 256, 256);
  split_wt_kernel<<<(65536 + 255) / 256, 256>>>(W2, wh + 65536, wl + 65536, 256, 256);
  split_wt_kernel<<<(32768 + 255) / 256, 256>>>(W3, wh + 131072, wl + 131072, 256, 128);
  split_wt_kernel<<<(8192 + 255) / 256, 256>>>(W4, wh + 163840, wl + 163840, 128, 64);

  // normalization + CSR build
  deg_init_kernel<<<(N + 255) / 256, 256>>>(N);
  deg_count_kernel<<<(E + 255) / 256, 256>>>(dstp, E);
  dinv_kernel<<<(N + 255) / 256, 256>>>(N);
  int nblk = (N + SCAN_BLK - 1) / SCAN_BLK;
  scan1_kernel<<<nblk, SCAN_BLK>>>(N);
  scan2_kernel<<<1, 64>>>(nblk);
  scan3_kernel<<<(N + 256) / 256, 256>>>(N, E);
  fill_kernel<<<(E + 255) / 256, 256>>>(src, dstp, E);

  const int MB = (N + 127) / 128;       // 391
  const int GW = (N * 32 + 255) / 256;  // warp per row

  // L1: 256->256
  gemm_bf16_kernel<128><<<dim3(MB, 2), 256, SM_128>>>(
      ah, al, wh, wl, tmp, N, 256, 256);
  gather_split_kernel<256><<<GW, 256>>>(tmp, b1, ah, al, N);

  // L2: 256->256
  gemm_bf16_kernel<128><<<dim3(MB, 2), 256, SM_128>>>(
      ah, al, wh + 65536, wl + 65536, tmp, N, 256, 256);
  gather_split_kernel<256><<<GW, 256>>>(tmp, b2, ah, al, N);

  // L3: 256->128
  gemm_bf16_kernel<128><<<dim3(MB, 1), 256, SM_128>>>(
      ah, al, wh + 131072, wl + 131072, tmp, N, 256, 128);
  gather_split_kernel<128><<<GW, 256>>>(tmp, b3, ah, al, N);

  // L4: 128->64
  gemm_bf16_kernel<64><<<dim3(MB, 1), 256, SM_64>>>(
      ah, al, wh + 163840, wl + 163840, tmp, N, 128, 64);
  gather_raw64_kernel<<<GW, 256>>>(tmp, y, N);

  // bias4 + lrelu + dropout + dense 64->10
  final_kernel<<<(N * 32 + 255) / 256, 256>>>(y, b4, W5, b5, (float*)d_out, N);
}

// round 11
// speedup vs baseline: 3.8863x; 1.0227x over previous
#include <cuda_runtime.h>
#include <cuda_bf16.h>
#include <stdint.h>

// ---------------------------------------------------------------------------
// ShallowGCNet: 4x GCNConv(lrelu) + dropout + dense
// N=50000, E=800000, features 256->256->256->128->64->10
// GEMM: bf16 double-split (3 products) m16n8k16 mma.sync + ldmatrix fragments,
// cp.async 2-stage pipeline. Aggregation: CSR gather (L2-BW-limited).
// ---------------------------------------------------------------------------

__device__ float g_tmp[50000 * 256];   // GEMM output / gather input
__device__ float g_y[50000 * 64];      // L4 gather output (raw)
__device__ __nv_bfloat16 g_ah[50000 * 256];  // A hi plane
__device__ __nv_bfloat16 g_al[50000 * 256];  // A lo plane
__device__ __nv_bfloat16 g_wh[172032];       // W^T hi  [Fout][K]
__device__ __nv_bfloat16 g_wl[172032];       // W^T lo
// offsets: w1=0 w2=65536 w3=131072 w4=163840
__device__ float g_dinv[50000];
__device__ int   g_deg[50000];
__device__ int   g_off[50001];
__device__ int   g_bsum[64];
__device__ int   g_fill[50000];
__device__ int   g_csr_src[800000];
__device__ float g_csr_w[800000];

// ------------------------------ degree ------------------------------------
__global__ void deg_init_kernel(int n) {
  int i = blockIdx.x * blockDim.x + threadIdx.x;
  if (i < n) { g_deg[i] = 0; g_fill[i] = 0; }
}
__global__ void deg_count_kernel(const int* __restrict__ dst, int E) {
  int e = blockIdx.x * blockDim.x + threadIdx.x;
  if (e < E) atomicAdd(&g_deg[dst[e]], 1);
}
__global__ void dinv_kernel(int n) {
  int i = blockIdx.x * blockDim.x + threadIdx.x;
  if (i < n) g_dinv[i] = 1.0f / sqrtf((float)(g_deg[i] + 1));
}

// ------------------------------ CSR build ----------------------------------
#define SCAN_BLK 1024
__global__ void scan1_kernel(int n) {
  __shared__ int sh[SCAN_BLK];
  int i = blockIdx.x * SCAN_BLK + threadIdx.x;
  int v = (i < n) ? g_deg[i] : 0;
  sh[threadIdx.x] = v;
  __syncthreads();
#pragma unroll
  for (int d = 1; d < SCAN_BLK; d <<= 1) {
    int t = (threadIdx.x >= d) ? sh[threadIdx.x - d] : 0;
    __syncthreads();
    sh[threadIdx.x] += t;
    __syncthreads();
  }
  if (i < n) g_off[i] = sh[threadIdx.x] - v;
  if (threadIdx.x == SCAN_BLK - 1) g_bsum[blockIdx.x] = sh[threadIdx.x];
}
__global__ void scan2_kernel(int nb) {
  __shared__ int sh[64];
  int v = (threadIdx.x < nb) ? g_bsum[threadIdx.x] : 0;
  sh[threadIdx.x] = v;
  __syncthreads();
#pragma unroll
  for (int d = 1; d < 64; d <<= 1) {
    int t = (threadIdx.x >= d) ? sh[threadIdx.x - d] : 0;
    __syncthreads();
    sh[threadIdx.x] += t;
    __syncthreads();
  }
  if (threadIdx.x < nb) g_bsum[threadIdx.x] = sh[threadIdx.x] - v;
}
__global__ void scan3_kernel(int n, int E) {
  int i = blockIdx.x * blockDim.x + threadIdx.x;
  if (i < n) g_off[i] += g_bsum[i >> 10];
  if (i == n) g_off[n] = E;
}
__global__ void fill_kernel(const int* __restrict__ src,
                            const int* __restrict__ dst, int E) {
  int e = blockIdx.x * blockDim.x + threadIdx.x;
  if (e >= E) return;
  int s = src[e], d = dst[e];
  int pos = g_off[d] + atomicAdd(&g_fill[d], 1);
  g_csr_src[pos] = s;
  g_csr_w[pos] = g_dinv[s];
}

// ------------------------- bf16 split helpers -------------------------------
__device__ __forceinline__ uint32_t pack_bf2(__nv_bfloat16 a, __nv_bfloat16 b) {
  return (uint32_t)__bfloat16_as_ushort(a) |
         ((uint32_t)__bfloat16_as_ushort(b) << 16);
}

__global__ void split_x_kernel(const float* __restrict__ x,
                               __nv_bfloat16* __restrict__ h,
                               __nv_bfloat16* __restrict__ l, int n) {
  int i = blockIdx.x * blockDim.x + threadIdx.x;
  if (i >= n) return;
  float v = x[i];
  __nv_bfloat16 hh = __float2bfloat16(v);
  h[i] = hh;
  l[i] = __float2bfloat16(v - __bfloat162float(hh));
}

__global__ void split_wt_kernel(const float* __restrict__ W,
                                __nv_bfloat16* __restrict__ h,
                                __nv_bfloat16* __restrict__ l,
                                int K, int Fout) {
  int i = blockIdx.x * blockDim.x + threadIdx.x;
  if (i >= K * Fout) return;
  int k = i / Fout, nn = i % Fout;
  float v = W[i];
  __nv_bfloat16 hh = __float2bfloat16(v);
  h[nn * K + k] = hh;
  l[nn * K + k] = __float2bfloat16(v - __bfloat162float(hh));
}

// ------------------------ bf16 mma GEMM ------------------------------------
__device__ __forceinline__ void cp16(uint32_t dst, const void* src) {
  asm volatile("cp.async.ca.shared.global [%0], [%1], 16;"
               :: "r"(dst), "l"(src));
}
__device__ __forceinline__ void cp_commit() {
  asm volatile("cp.async.commit_group;");
}
template<int n> __device__ __forceinline__ void cp_wait() {
  asm volatile("cp.async.wait_group %0;" :: "n"(n));
}

#define MMA_BF16(c, a, b)                                              \
  asm volatile(                                                        \
      "mma.sync.aligned.m16n8k16.row.col.f32.bf16.bf16.f32 "           \
      "{%0,%1,%2,%3}, {%4,%5,%6,%7}, {%8,%9}, {%0,%1,%2,%3};"          \
      : "+f"((c)[0]), "+f"((c)[1]), "+f"((c)[2]), "+f"((c)[3])         \
      : "r"((a)[0]), "r"((a)[1]), "r"((a)[2]), "r"((a)[3]),            \
        "r"((b)[0]), "r"((b)[1]))

#define LDM4(r, addr)                                                  \
  asm volatile("ldmatrix.sync.aligned.m8n8.x4.shared.b16 "             \
               "{%0,%1,%2,%3}, [%4];"                                  \
               : "=r"((r)[0]), "=r"((r)[1]), "=r"((r)[2]), "=r"((r)[3])\
               : "r"(addr))

// C[:, col0:col0+BN] = (Ah+Al) @ (Bh+Bl)^T   (3-product bf16 split)
// A planes [N][K] k-major, B planes [Fout][K] k-major. BM=128, BK=32,
// 8 warps 4m x 2n; warp tile 32 x BN/2. Smem row stride 80B: 80r mod 128 is
// a bijection over 8 rows -> every ldmatrix phase is bank-conflict-free.
template<int BN>
__global__ void __launch_bounds__(256, 1) gemm_bf16_kernel(
    const __nv_bfloat16* __restrict__ Ah, const __nv_bfloat16* __restrict__ Al,
    const __nv_bfloat16* __restrict__ Bh, const __nv_bfloat16* __restrict__ Bl,
    float* __restrict__ C, int N, int K, int Fout) {
  constexpr int SB = BN * 80;            // one B plane per stage (bytes)
  constexpr int ST = 20480 + 2 * SB;     // stage size (A 2x10240 + B 2xSB)
  constexpr int NA = BN / 16;            // n-atoms per warp
  constexpr int NP = NA / 2;             // ldmatrix x4 atom-pairs
  extern __shared__ char smc[];
  const uint32_t smu = (uint32_t)__cvta_generic_to_shared(smc);

  const int tid = threadIdx.x;
  const int wid = tid >> 5, lane = tid & 31;
  const int wm = wid & 3, wn = wid >> 2;
  const int row0 = blockIdx.x * 128;
  const int col0 = blockIdx.y * BN;
  const int NIT = K >> 5;

  // ldmatrix address patterns (relative to stage base)
  // A x4 (m16k16): lanes 0-15 -> rows, lane>=16 -> k+8 half
  const uint32_t a_rel =
      (uint32_t)(wm * 32 + (lane & 15)) * 80u + (uint32_t)(lane >> 4) * 16u;
  // B x4 (two n8k16 atoms): row = (lane&7) + 8*(lane>=16), bit3 -> k+8 half
  const uint32_t b_rel = 20480u +
      (uint32_t)(wn * (BN / 2) + (lane & 7) + ((lane >> 4) << 3)) * 80u +
      (uint32_t)((lane >> 3) & 1) * 16u;

  float c[2][NA][4] = {};

  auto load_stage = [&](int s, int k0) {
    uint32_t sb = smu + (uint32_t)s * ST;
    int r = tid >> 2, q = tid & 3;
#pragma unroll
    for (int p = 0; p < 2; ++p) {               // A: 128 rows
      int rr = r + p * 64;
      int grow = row0 + rr; if (grow >= N) grow = N - 1;  // clamp (rows unused)
      cp16(sb + rr * 80 + q * 16, Ah + (size_t)grow * K + k0 + q * 8);
      cp16(sb + 10240 + rr * 80 + q * 16, Al + (size_t)grow * K + k0 + q * 8);
    }
#pragma unroll
    for (int p = 0; p < BN / 64; ++p) {         // B: BN rows
      int rr = r + p * 64;
      int gc = col0 + rr;
      cp16(sb + 20480 + rr * 80 + q * 16, Bh + (size_t)gc * K + k0 + q * 8);
      cp16(sb + 20480 + SB + rr * 80 + q * 16, Bl + (size_t)gc * K + k0 + q * 8);
    }
  };

  load_stage(0, 0);
  cp_commit();
  for (int it = 0; it < NIT; ++it) {
    if (it + 1 < NIT) {
      load_stage((it + 1) & 1, (it + 1) * 32);
      cp_commit();
      cp_wait<1>();
    } else {
      cp_wait<0>();
    }
    __syncthreads();
    uint32_t sbu = smu + (uint32_t)(it & 1) * ST;
#pragma unroll
    for (int ka = 0; ka < 2; ++ka) {
      uint32_t ah[2][4], al[2][4];
#pragma unroll
      for (int ma = 0; ma < 2; ++ma) {
        uint32_t base = sbu + a_rel + (uint32_t)ma * 1280u + (uint32_t)ka * 32u;
        LDM4(ah[ma], base);
        LDM4(al[ma], base + 10240u);
      }
      uint32_t bh[NA][2], bl[NA][2];
#pragma unroll
      for (int p = 0; p < NP; ++p) {
        uint32_t base = sbu + b_rel + (uint32_t)p * (16u * 80u) + (uint32_t)ka * 32u;
        uint32_t r[4];
        LDM4(r, base);
        bh[2 * p][0] = r[0]; bh[2 * p][1] = r[1];
        bh[2 * p + 1][0] = r[2]; bh[2 * p + 1][1] = r[3];
        LDM4(r, base + (uint32_t)SB);
        bl[2 * p][0] = r[0]; bl[2 * p][1] = r[1];
        bl[2 * p + 1][0] = r[2]; bl[2 * p + 1][1] = r[3];
      }
#pragma unroll
      for (int ma = 0; ma < 2; ++ma)
#pragma unroll
        for (int na = 0; na < NA; ++na) {
          MMA_BF16(c[ma][na], ah[ma], bh[na]);
          MMA_BF16(c[ma][na], al[ma], bh[na]);
          MMA_BF16(c[ma][na], ah[ma], bl[na]);
        }
    }
    __syncthreads();
  }

  const int gq = lane >> 2, tq = lane & 3;
#pragma unroll
  for (int ma = 0; ma < 2; ++ma) {
    int row = row0 + wm * 32 + ma * 16 + gq;
#pragma unroll
    for (int na = 0; na < NA; ++na) {
      int col = col0 + wn * (BN / 2) + na * 8 + tq * 2;
      if (row < N)
        *(float2*)(C + (size_t)row * Fout + col) =
            make_float2(c[ma][na][0], c[ma][na][1]);
      if (row + 8 < N)
        *(float2*)(C + (size_t)(row + 8) * Fout + col) =
            make_float2(c[ma][na][2], c[ma][na][3]);
    }
  }
}

// -------------- CSR gather + fused bias/lrelu/bf16-split --------------------
template<int F>
__global__ void gather_split_kernel(const float* __restrict__ tmp,
                                    const float* __restrict__ bias,
                                    __nv_bfloat16* __restrict__ oh,
                                    __nv_bfloat16* __restrict__ ol, int n) {
  int w = (blockIdx.x * blockDim.x + threadIdx.x) >> 5;
  int lane = threadIdx.x & 31;
  if (w >= n) return;
  int beg = g_off[w], end = g_off[w + 1];
  float dr = g_dinv[w];
  constexpr int NV = F / 128;
  float4 acc[NV];
  const float4* self = (const float4*)(tmp + (size_t)w * F);
#pragma unroll
  for (int v = 0; v < NV; ++v) {
    float4 x = self[lane + 32 * v];
    acc[v] = make_float4(x.x * dr, x.y * dr, x.z * dr, x.w * dr);
  }
  for (int e0 = beg; e0 < end; e0 += 32) {
    int ne = min(32, end - e0);
    int s = 0; float ww = 0.f;
    if (lane < ne) { s = g_csr_src[e0 + lane]; ww = g_csr_w[e0 + lane]; }
    for (int j = 0; j < ne; ++j) {
      int sj = __shfl_sync(0xffffffffu, s, j);
      float wj = __shfl_sync(0xffffffffu, ww, j);
      const float4* sr = (const float4*)(tmp + (size_t)sj * F);
#pragma unroll
      for (int v = 0; v < NV; ++v) {
        float4 x = sr[lane + 32 * v];
        acc[v].x += wj * x.x; acc[v].y += wj * x.y;
        acc[v].z += wj * x.z; acc[v].w += wj * x.w;
      }
    }
  }
  uint32_t* ph = (uint32_t*)(oh + (size_t)w * F);
  uint32_t* pl = (uint32_t*)(ol + (size_t)w * F);
#pragma unroll
  for (int v = 0; v < NV; ++v) {
    int cb = lane + 32 * v;
    float4 b = *(const float4*)(bias + 4 * cb);
    float4 z = make_float4(acc[v].x * dr + b.x, acc[v].y * dr + b.y,
                           acc[v].z * dr + b.z, acc[v].w * dr + b.w);
    z.x = z.x > 0.f ? z.x : 0.01f * z.x;
    z.y = z.y > 0.f ? z.y : 0.01f * z.y;
    z.z = z.z > 0.f ? z.z : 0.01f * z.z;
    z.w = z.w > 0.f ? z.w : 0.01f * z.w;
    __nv_bfloat16 hx = __float2bfloat16(z.x), hy = __float2bfloat16(z.y);
    __nv_bfloat16 hz = __float2bfloat16(z.z), hw = __float2bfloat16(z.w);
    ph[2 * cb + 0] = pack_bf2(hx, hy);
    ph[2 * cb + 1] = pack_bf2(hz, hw);
    pl[2 * cb + 0] = pack_bf2(__float2bfloat16(z.x - __bfloat162float(hx)),
                              __float2bfloat16(z.y - __bfloat162float(hy)));
    pl[2 * cb + 1] = pack_bf2(__float2bfloat16(z.z - __bfloat162float(hz)),
                              __float2bfloat16(z.w - __bfloat162float(hw)));
  }
}

__global__ void gather_raw64_kernel(const float* __restrict__ tmp,
                                    float* __restrict__ out, int n) {
  int w = (blockIdx.x * blockDim.x + threadIdx.x) >> 5;
  int lane = threadIdx.x & 31;
  if (w >= n) return;
  int beg = g_off[w], end = g_off[w + 1];
  float dr = g_dinv[w];
  float2 acc;
  {
    float2 x = ((const float2*)(tmp + (size_t)w * 64))[lane];
    acc = make_float2(x.x * dr, x.y * dr);
  }
  for (int e0 = beg; e0 < end; e0 += 32) {
    int ne = min(32, end - e0);
    int s = 0; float ww = 0.f;
    if (lane < ne) { s = g_csr_src[e0 + lane]; ww = g_csr_w[e0 + lane]; }
    for (int j = 0; j < ne; ++j) {
      int sj = __shfl_sync(0xffffffffu, s, j);
      float wj = __shfl_sync(0xffffffffu, ww, j);
      float2 x = ((const float2*)(tmp + (size_t)sj * 64))[lane];
      acc.x += wj * x.x; acc.y += wj * x.y;
    }
  }
  ((float2*)(out + (size_t)w * 64))[lane] = make_float2(acc.x * dr, acc.y * dr);
}

// ------------------- dropout (JAX threefry) + dense -------------------------
#define TF_ROUND(x0, x1, r)                         \
  { x0 += x1; x1 = (x1 << (r)) | (x1 >> (32 - (r))); x1 ^= x0; }

__device__ __forceinline__ uint32_t threefry_bits(uint32_t idx) {
  const uint32_t k0 = 0u, k1 = 42u;
  const uint32_t k2 = 0x1BD11BDAu ^ k0 ^ k1;
  uint32_t x0 = 0u, x1 = idx;
  x0 += k0; x1 += k1;
  TF_ROUND(x0, x1, 13) TF_ROUND(x0, x1, 15) TF_ROUND(x0, x1, 26) TF_ROUND(x0, x1, 6)
  x0 += k1; x1 += k2 + 1u;
  TF_ROUND(x0, x1, 17) TF_ROUND(x0, x1, 29) TF_ROUND(x0, x1, 16) TF_ROUND(x0, x1, 24)
  x0 += k2; x1 += k0 + 2u;
  TF_ROUND(x0, x1, 13) TF_ROUND(x0, x1, 15) TF_ROUND(x0, x1, 26) TF_ROUND(x0, x1, 6)
  x0 += k0; x1 += k1 + 3u;
  TF_ROUND(x0, x1, 17) TF_ROUND(x0, x1, 29) TF_ROUND(x0, x1, 16) TF_ROUND(x0, x1, 24)
  x0 += k1; x1 += k2 + 4u;
  TF_ROUND(x0, x1, 13) TF_ROUND(x0, x1, 15) TF_ROUND(x0, x1, 26) TF_ROUND(x0, x1, 6)
  x0 += k2; x1 += k0 + 5u;
  return x0 ^ x1;
}

__global__ void final_kernel(const float* __restrict__ h,
                             const float* __restrict__ b4,
                             const float* __restrict__ W5,
                             const float* __restrict__ b5,
                             float* __restrict__ out, int n) {
  __shared__ float w5s[640];
  __shared__ float b5s[16];
  for (int i = threadIdx.x; i < 640; i += blockDim.x) w5s[i] = W5[i];
  if (threadIdx.x < 10) b5s[threadIdx.x] = b5[threadIdx.x];
  __syncthreads();
  int gw = (blockIdx.x * blockDim.x + threadIdx.x) >> 5;
  int lane = threadIdx.x & 31;
  if (gw >= n) return;
  int i = gw;
  float v0 = h[i * 64 + lane] + b4[lane];
  v0 = (v0 > 0.f) ? v0 : 0.01f * v0;
  float v1 = h[i * 64 + lane + 32] + b4[lane + 32];
  v1 = (v1 > 0.f) ? v1 : 0.01f * v1;
  uint32_t bits0 = threefry_bits((uint32_t)(i * 64 + lane));
  uint32_t bits1 = threefry_bits((uint32_t)(i * 64 + lane + 32));
  v0 = (bits0 & 0x80000000u) ? 0.f : v0 * 2.f;
  v1 = (bits1 & 0x80000000u) ? 0.f : v1 * 2.f;
#pragma unroll
  for (int j = 0; j < 10; ++j) {
    float p = v0 * w5s[lane * 10 + j] + v1 * w5s[(lane + 32) * 10 + j];
#pragma unroll
    for (int off = 16; off; off >>= 1)
      p += __shfl_xor_sync(0xffffffffu, p, off);
    if (lane == 0) out[i * 10 + j] = p + b5s[j];
  }
}

// ------------------------------ launch -------------------------------------
extern "C" void kernel_launch(void* const* d_in, const int* in_sizes, int n_in,
                              void* d_out, int out_size) {
  const float* x = (const float*)d_in[0];
  const int* ei = (const int*)d_in[1];   // int32
  const float* W1 = (const float*)d_in[2];
  const float* b1 = (const float*)d_in[3];
  const float* W2 = (const float*)d_in[4];
  const float* b2 = (const float*)d_in[5];
  const float* W3 = (const float*)d_in[6];
  const float* b3 = (const float*)d_in[7];
  const float* W4 = (const float*)d_in[8];
  const float* b4 = (const float*)d_in[9];
  const float* W5 = (const float*)d_in[10];
  const float* b5 = (const float*)d_in[11];
  const int N = in_sizes[0] / 256;
  const int E = in_sizes[1] / 2;
  const int* src = ei;
  const int* dstp = ei + E;

  float* tmp = nullptr; float* y = nullptr;
  __nv_bfloat16 *ah = nullptr, *al = nullptr, *wh = nullptr, *wl = nullptr;
  cudaGetSymbolAddress((void**)&tmp, g_tmp);
  cudaGetSymbolAddress((void**)&y, g_y);
  cudaGetSymbolAddress((void**)&ah, g_ah);
  cudaGetSymbolAddress((void**)&al, g_al);
  cudaGetSymbolAddress((void**)&wh, g_wh);
  cudaGetSymbolAddress((void**)&wl, g_wl);

  constexpr int SM_128 = 2 * (20480 + 2 * 128 * 80);  // 81920
  constexpr int SM_64  = 2 * (20480 + 2 * 64 * 80);   // 61440
  cudaFuncSetAttribute(gemm_bf16_kernel<128>,
                       cudaFuncAttributeMaxDynamicSharedMemorySize, SM_128);
  cudaFuncSetAttribute(gemm_bf16_kernel<64>,
                       cudaFuncAttributeMaxDynamicSharedMemorySize, SM_64);

  // operand splits
  split_x_kernel<<<(N * 256 + 255) / 256, 256>>>(x, ah, al, N * 256);
  split_wt_kernel<<<(65536 + 255) / 256, 256>>>(W1, wh, wl, 256, 256);
  split_wt_kernel<<<(65536 + 255) / 256, 256>>>(W2, wh + 65536, wl + 65536, 256, 256);
  split_wt_kernel<<<(32768 + 255) / 256, 256>>>(W3, wh + 131072, wl + 131072, 256, 128);
  split_wt_kernel<<<(8192 + 255) / 256, 256>>>(W4, wh + 163840, wl + 163840, 128, 64);

  // normalization + CSR build
  deg_init_kernel<<<(N + 255) / 256, 256>>>(N);
  deg_count_kernel<<<(E + 255) / 256, 256>>>(dstp, E);
  dinv_kernel<<<(N + 255) / 256, 256>>>(N);
  int nblk = (N + SCAN_BLK - 1) / SCAN_BLK;
  scan1_kernel<<<nblk, SCAN_BLK>>>(N);
  scan2_kernel<<<1, 64>>>(nblk);
  scan3_kernel<<<(N + 256) / 256, 256>>>(N, E);
  fill_kernel<<<(E + 255) / 256, 256>>>(src, dstp, E);

  const int MB = (N + 127) / 128;       // 391
  const int GW = (N * 32 + 255) / 256;  // warp per row

  // L1: 256->256
  gemm_bf16_kernel<128><<<dim3(MB, 2), 256, SM_128>>>(
      ah, al, wh, wl, tmp, N, 256, 256);
  gather_split_kernel<256><<<GW, 256>>>(tmp, b1, ah, al, N);

  // L2: 256->256
  gemm_bf16_kernel<128><<<dim3(MB, 2), 256, SM_128>>>(
      ah, al, wh + 65536, wl + 65536, tmp, N, 256, 256);
  gather_split_kernel<256><<<GW, 256>>>(tmp, b2, ah, al, N);

  // L3: 256->128
  gemm_bf16_kernel<128><<<dim3(MB, 1), 256, SM_128>>>(
      ah, al, wh + 131072, wl + 131072, tmp, N, 256, 128);
  gather_split_kernel<128><<<GW, 256>>>(tmp, b3, ah, al, N);

  // L4: 128->64
  gemm_bf16_kernel<64><<<dim3(MB, 1), 256, SM_64>>>(
      ah, al, wh + 163840, wl + 163840, tmp, N, 128, 64);
  gather_raw64_kernel<<<GW, 256>>>(tmp, y, N);

  // bias4 + lrelu + dropout + dense 64->10
  final_kernel<<<(N * 32 + 255) / 256, 256>>>(y, b4, W5, b5, (float*)d_out, N);
}

// round 12
// speedup vs baseline: 4.1554x; 1.0693x over previous
#include <cuda_runtime.h>
#include <cuda_bf16.h>
#include <stdint.h>

// ---------------------------------------------------------------------------
// ShallowGCNet: 4x GCNConv(lrelu) + dropout + dense
// N=50000, E=800000, features 256->256->256->128->64->10
// GEMM: bf16 double-split (3 products) m16n8k16 mma.sync + ldmatrix,
// cp.async 2-stage pipeline, 2 CTAs/SM. Aggregation: CSR gather (L2-bound).
// ---------------------------------------------------------------------------

__device__ float g_tmp[50000 * 256];   // GEMM output / gather input
__device__ float g_y[50000 * 64];      // L4 gather output (raw)
__device__ __nv_bfloat16 g_ah[50000 * 256];  // A hi plane
__device__ __nv_bfloat16 g_al[50000 * 256];  // A lo plane
__device__ __nv_bfloat16 g_wh[172032];       // W^T hi  [Fout][K]
__device__ __nv_bfloat16 g_wl[172032];       // W^T lo
// offsets: w1=0 w2=65536 w3=131072 w4=163840
__device__ float g_dinv[50000];
__device__ int   g_deg[50000];
__device__ int   g_off[50001];
__device__ int   g_bsum[64];
__device__ int   g_fill[50000];
__device__ int   g_csr_src[800000];
__device__ float g_csr_w[800000];

// ------------------------------ degree ------------------------------------
__global__ void deg_init_kernel(int n) {
  int i = blockIdx.x * blockDim.x + threadIdx.x;
  if (i < n) { g_deg[i] = 0; g_fill[i] = 0; }
}
__global__ void deg_count_kernel(const int* __restrict__ dst, int E) {
  int e = blockIdx.x * blockDim.x + threadIdx.x;
  if (e < E) atomicAdd(&g_deg[dst[e]], 1);
}
__global__ void dinv_kernel(int n) {
  int i = blockIdx.x * blockDim.x + threadIdx.x;
  if (i < n) g_dinv[i] = 1.0f / sqrtf((float)(g_deg[i] + 1));
}

// ------------------------------ CSR build ----------------------------------
#define SCAN_BLK 1024
__global__ void scan1_kernel(int n) {
  __shared__ int sh[SCAN_BLK];
  int i = blockIdx.x * SCAN_BLK + threadIdx.x;
  int v = (i < n) ? g_deg[i] : 0;
  sh[threadIdx.x] = v;
  __syncthreads();
#pragma unroll
  for (int d = 1; d < SCAN_BLK; d <<= 1) {
    int t = (threadIdx.x >= d) ? sh[threadIdx.x - d] : 0;
    __syncthreads();
    sh[threadIdx.x] += t;
    __syncthreads();
  }
  if (i < n) g_off[i] = sh[threadIdx.x] - v;
  if (threadIdx.x == SCAN_BLK - 1) g_bsum[blockIdx.x] = sh[threadIdx.x];
}
__global__ void scan2_kernel(int nb) {
  __shared__ int sh[64];
  int v = (threadIdx.x < nb) ? g_bsum[threadIdx.x] : 0;
  sh[threadIdx.x] = v;
  __syncthreads();
#pragma unroll
  for (int d = 1; d < 64; d <<= 1) {
    int t = (threadIdx.x >= d) ? sh[threadIdx.x - d] : 0;
    __syncthreads();
    sh[threadIdx.x] += t;
    __syncthreads();
  }
  if (threadIdx.x < nb) g_bsum[threadIdx.x] = sh[threadIdx.x] - v;
}
__global__ void scan3_kernel(int n, int E) {
  int i = blockIdx.x * blockDim.x + threadIdx.x;
  if (i < n) g_off[i] += g_bsum[i >> 10];
  if (i == n) g_off[n] = E;
}
__global__ void fill_kernel(const int* __restrict__ src,
                            const int* __restrict__ dst, int E) {
  int e = blockIdx.x * blockDim.x + threadIdx.x;
  if (e >= E) return;
  int s = src[e], d = dst[e];
  int pos = g_off[d] + atomicAdd(&g_fill[d], 1);
  g_csr_src[pos] = s;
  g_csr_w[pos] = g_dinv[s];
}

// ------------------------- bf16 split helpers -------------------------------
__device__ __forceinline__ uint32_t pack_bf2(__nv_bfloat16 a, __nv_bfloat16 b) {
  return (uint32_t)__bfloat16_as_ushort(a) |
         ((uint32_t)__bfloat16_as_ushort(b) << 16);
}

__global__ void split_x_kernel(const float* __restrict__ x,
                               __nv_bfloat16* __restrict__ h,
                               __nv_bfloat16* __restrict__ l, int n) {
  int i = blockIdx.x * blockDim.x + threadIdx.x;
  if (i >= n) return;
  float v = x[i];
  __nv_bfloat16 hh = __float2bfloat16(v);
  h[i] = hh;
  l[i] = __float2bfloat16(v - __bfloat162float(hh));
}

// All four W matrices -> transposed hi/lo planes, single launch.
__global__ void split_wt_all_kernel(const float* __restrict__ W1,
                                    const float* __restrict__ W2,
                                    const float* __restrict__ W3,
                                    const float* __restrict__ W4,
                                    __nv_bfloat16* __restrict__ h,
                                    __nv_bfloat16* __restrict__ l) {
  int i = blockIdx.x * blockDim.x + threadIdx.x;
  if (i >= 172032) return;
  const float* W; int K, F, base, i0;
  if (i < 65536)        { W = W1; K = 256; F = 256; base = 0;      i0 = i; }
  else if (i < 131072)  { W = W2; K = 256; F = 256; base = 65536;  i0 = i - 65536; }
  else if (i < 163840)  { W = W3; K = 256; F = 128; base = 131072; i0 = i - 131072; }
  else                  { W = W4; K = 128; F = 64;  base = 163840; i0 = i - 163840; }
  int k = i0 / F, nn = i0 % F;
  float v = W[i0];
  __nv_bfloat16 hh = __float2bfloat16(v);
  h[base + nn * K + k] = hh;
  l[base + nn * K + k] = __float2bfloat16(v - __bfloat162float(hh));
}

// ------------------------ bf16 mma GEMM ------------------------------------
__device__ __forceinline__ void cp16(uint32_t dst, const void* src) {
  asm volatile("cp.async.ca.shared.global [%0], [%1], 16;"
               :: "r"(dst), "l"(src));
}
__device__ __forceinline__ void cp_commit() {
  asm volatile("cp.async.commit_group;");
}
template<int n> __device__ __forceinline__ void cp_wait() {
  asm volatile("cp.async.wait_group %0;" :: "n"(n));
}

#define MMA_BF16(c, a, b0, b1)                                         \
  asm volatile(                                                        \
      "mma.sync.aligned.m16n8k16.row.col.f32.bf16.bf16.f32 "           \
      "{%0,%1,%2,%3}, {%4,%5,%6,%7}, {%8,%9}, {%0,%1,%2,%3};"          \
      : "+f"((c)[0]), "+f"((c)[1]), "+f"((c)[2]), "+f"((c)[3])         \
      : "r"((a)[0]), "r"((a)[1]), "r"((a)[2]), "r"((a)[3]),            \
        "r"(b0), "r"(b1))

#define LDM4(r, addr)                                                  \
  asm volatile("ldmatrix.sync.aligned.m8n8.x4.shared.b16 "             \
               "{%0,%1,%2,%3}, [%4];"                                  \
               : "=r"((r)[0]), "=r"((r)[1]), "=r"((r)[2]), "=r"((r)[3])\
               : "r"(addr))

// C[:, col0:col0+BN] = (Ah+Al) @ (Bh+Bl)^T   (3-product bf16 split)
// BM=128, BK=32, 8 warps 4m x 2n; 2 CTAs/SM for latency hiding.
// B fragments are consumed immediately after load to bound live registers.
template<int BN>
__global__ void __launch_bounds__(256, 2) gemm_bf16_kernel(
    const __nv_bfloat16* __restrict__ Ah, const __nv_bfloat16* __restrict__ Al,
    const __nv_bfloat16* __restrict__ Bh, const __nv_bfloat16* __restrict__ Bl,
    float* __restrict__ C, int N, int K, int Fout) {
  constexpr int SB = BN * 80;            // one B plane per stage (bytes)
  constexpr int ST = 20480 + 2 * SB;     // stage size
  constexpr int NA = BN / 16;            // n-atoms per warp
  constexpr int NP = NA / 2;             // ldmatrix x4 atom-pairs
  extern __shared__ char smc[];
  const uint32_t smu = (uint32_t)__cvta_generic_to_shared(smc);

  const int tid = threadIdx.x;
  const int wid = tid >> 5, lane = tid & 31;
  const int wm = wid & 3, wn = wid >> 2;
  const int row0 = blockIdx.x * 128;
  const int col0 = blockIdx.y * BN;
  const int NIT = K >> 5;

  // A x4 (m16k16): lanes 0-15 -> rows, lane>=16 -> k+8 half
  const uint32_t a_rel =
      (uint32_t)(wm * 32 + (lane & 15)) * 80u + (uint32_t)(lane >> 4) * 16u;
  // B x4 (two n8k16 atoms): row = (lane&7) + 8*(lane>=16), bit3 -> k+8 half
  const uint32_t b_rel = 20480u +
      (uint32_t)(wn * (BN / 2) + (lane & 7) + ((lane >> 4) << 3)) * 80u +
      (uint32_t)((lane >> 3) & 1) * 16u;

  float c[2][NA][4] = {};

  auto load_stage = [&](int s, int k0) {
    uint32_t sb = smu + (uint32_t)s * ST;
    int r = tid >> 2, q = tid & 3;
#pragma unroll
    for (int p = 0; p < 2; ++p) {               // A: 128 rows
      int rr = r + p * 64;
      int grow = row0 + rr; if (grow >= N) grow = N - 1;  // clamp (rows unused)
      cp16(sb + rr * 80 + q * 16, Ah + (size_t)grow * K + k0 + q * 8);
      cp16(sb + 10240 + rr * 80 + q * 16, Al + (size_t)grow * K + k0 + q * 8);
    }
#pragma unroll
    for (int p = 0; p < BN / 64; ++p) {         // B: BN rows
      int rr = r + p * 64;
      int gc = col0 + rr;
      cp16(sb + 20480 + rr * 80 + q * 16, Bh + (size_t)gc * K + k0 + q * 8);
      cp16(sb + 20480 + SB + rr * 80 + q * 16, Bl + (size_t)gc * K + k0 + q * 8);
    }
  };

  load_stage(0, 0);
  cp_commit();
  for (int it = 0; it < NIT; ++it) {
    if (it + 1 < NIT) {
      load_stage((it + 1) & 1, (it + 1) * 32);
      cp_commit();
      cp_wait<1>();
    } else {
      cp_wait<0>();
    }
    __syncthreads();
    uint32_t sbu = smu + (uint32_t)(it & 1) * ST;
#pragma unroll
    for (int ka = 0; ka < 2; ++ka) {
      uint32_t ah[2][4], al[2][4];
#pragma unroll
      for (int ma = 0; ma < 2; ++ma) {
        uint32_t base = sbu + a_rel + (uint32_t)ma * 1280u + (uint32_t)ka * 32u;
        LDM4(ah[ma], base);
        LDM4(al[ma], base + 10240u);
      }
#pragma unroll
      for (int p = 0; p < NP; ++p) {
        uint32_t base = sbu + b_rel + (uint32_t)p * (16u * 80u) + (uint32_t)ka * 32u;
        uint32_t rb[4], rl[4];
        LDM4(rb, base);
        LDM4(rl, base + (uint32_t)SB);
#pragma unroll
        for (int ma = 0; ma < 2; ++ma) {
          MMA_BF16(c[ma][2 * p],     ah[ma], rb[0], rb[1]);
          MMA_BF16(c[ma][2 * p],     al[ma], rb[0], rb[1]);
          MMA_BF16(c[ma][2 * p],     ah[ma], rl[0], rl[1]);
          MMA_BF16(c[ma][2 * p + 1], ah[ma], rb[2], rb[3]);
          MMA_BF16(c[ma][2 * p + 1], al[ma], rb[2], rb[3]);
          MMA_BF16(c[ma][2 * p + 1], ah[ma], rl[2], rl[3]);
        }
      }
    }
    __syncthreads();
  }

  const int gq = lane >> 2, tq = lane & 3;
#pragma unroll
  for (int ma = 0; ma < 2; ++ma) {
    int row = row0 + wm * 32 + ma * 16 + gq;
#pragma unroll
    for (int na = 0; na < NA; ++na) {
      int col = col0 + wn * (BN / 2) + na * 8 + tq * 2;
      if (row < N)
        *(float2*)(C + (size_t)row * Fout + col) =
            make_float2(c[ma][na][0], c[ma][na][1]);
      if (row + 8 < N)
        *(float2*)(C + (size_t)(row + 8) * Fout + col) =
            make_float2(c[ma][na][2], c[ma][na][3]);
    }
  }
}

// -------------- CSR gather + fused bias/lrelu/bf16-split --------------------
template<int F>
__global__ void gather_split_kernel(const float* __restrict__ tmp,
                                    const float* __restrict__ bias,
                                    __nv_bfloat16* __restrict__ oh,
                                    __nv_bfloat16* __restrict__ ol, int n) {
  int w = (blockIdx.x * blockDim.x + threadIdx.x) >> 5;
  int lane = threadIdx.x & 31;
  if (w >= n) return;
  int beg = g_off[w], end = g_off[w + 1];
  float dr = g_dinv[w];
  constexpr int NV = F / 128;
  float4 acc[NV];
  const float4* self = (const float4*)(tmp + (size_t)w * F);
#pragma unroll
  for (int v = 0; v < NV; ++v) {
    float4 x = self[lane + 32 * v];
    acc[v] = make_float4(x.x * dr, x.y * dr, x.z * dr, x.w * dr);
  }
  for (int e0 = beg; e0 < end; e0 += 32) {
    int ne = min(32, end - e0);
    int s = 0; float ww = 0.f;
    if (lane < ne) { s = g_csr_src[e0 + lane]; ww = g_csr_w[e0 + lane]; }
    for (int j = 0; j < ne; ++j) {
      int sj = __shfl_sync(0xffffffffu, s, j);
      float wj = __shfl_sync(0xffffffffu, ww, j);
      const float4* sr = (const float4*)(tmp + (size_t)sj * F);
#pragma unroll
      for (int v = 0; v < NV; ++v) {
        float4 x = sr[lane + 32 * v];
        acc[v].x += wj * x.x; acc[v].y += wj * x.y;
        acc[v].z += wj * x.z; acc[v].w += wj * x.w;
      }
    }
  }
  uint32_t* ph = (uint32_t*)(oh + (size_t)w * F);
  uint32_t* pl = (uint32_t*)(ol + (size_t)w * F);
#pragma unroll
  for (int v = 0; v < NV; ++v) {
    int cb = lane + 32 * v;
    float4 b = *(const float4*)(bias + 4 * cb);
    float4 z = make_float4(acc[v].x * dr + b.x, acc[v].y * dr + b.y,
                           acc[v].z * dr + b.z, acc[v].w * dr + b.w);
    z.x = z.x > 0.f ? z.x : 0.01f * z.x;
    z.y = z.y > 0.f ? z.y : 0.01f * z.y;
    z.z = z.z > 0.f ? z.z : 0.01f * z.z;
    z.w = z.w > 0.f ? z.w : 0.01f * z.w;
    __nv_bfloat16 hx = __float2bfloat16(z.x), hy = __float2bfloat16(z.y);
    __nv_bfloat16 hz = __float2bfloat16(z.z), hw = __float2bfloat16(z.w);
    ph[2 * cb + 0] = pack_bf2(hx, hy);
    ph[2 * cb + 1] = pack_bf2(hz, hw);
    pl[2 * cb + 0] = pack_bf2(__float2bfloat16(z.x - __bfloat162float(hx)),
                              __float2bfloat16(z.y - __bfloat162float(hy)));
    pl[2 * cb + 1] = pack_bf2(__float2bfloat16(z.z - __bfloat162float(hz)),
                              __float2bfloat16(z.w - __bfloat162float(hw)));
  }
}

__global__ void gather_raw64_kernel(const float* __restrict__ tmp,
                                    float* __restrict__ out, int n) {
  int w = (blockIdx.x * blockDim.x + threadIdx.x) >> 5;
  int lane = threadIdx.x & 31;
  if (w >= n) return;
  int beg = g_off[w], end = g_off[w + 1];
  float dr = g_dinv[w];
  float2 acc;
  {
    float2 x = ((const float2*)(tmp + (size_t)w * 64))[lane];
    acc = make_float2(x.x * dr, x.y * dr);
  }
  for (int e0 = beg; e0 < end; e0 += 32) {
    int ne = min(32, end - e0);
    int s = 0; float ww = 0.f;
    if (lane < ne) { s = g_csr_src[e0 + lane]; ww = g_csr_w[e0 + lane]; }
    for (int j = 0; j < ne; ++j) {
      int sj = __shfl_sync(0xffffffffu, s, j);
      float wj = __shfl_sync(0xffffffffu, ww, j);
      float2 x = ((const float2*)(tmp + (size_t)sj * 64))[lane];
      acc.x += wj * x.x; acc.y += wj * x.y;
    }
  }
  ((float2*)(out + (size_t)w * 64))[lane] = make_float2(acc.x * dr, acc.y * dr);
}

// ------------------- dropout (JAX threefry) + dense -------------------------
#define TF_ROUND(x0, x1, r)                         \
  { x0 += x1; x1 = (x1 << (r)) | (x1 >> (32 - (r))); x1 ^= x0; }

__device__ __forceinline__ uint32_t threefry_bits(uint32_t idx) {
  const uint32_t k0 = 0u, k1 = 42u;
  const uint32_t k2 = 0x1BD11BDAu ^ k0 ^ k1;
  uint32_t x0 = 0u, x1 = idx;
  x0 += k0; x1 += k1;
  TF_ROUND(x0, x1, 13) TF_ROUND(x0, x1, 15) TF_ROUND(x0, x1, 26) TF_ROUND(x0, x1, 6)
  x0 += k1; x1 += k2 + 1u;
  TF_ROUND(x0, x1, 17) TF_ROUND(x0, x1, 29) TF_ROUND(x0, x1, 16) TF_ROUND(x0, x1, 24)
  x0 += k2; x1 += k0 + 2u;
  TF_ROUND(x0, x1, 13) TF_ROUND(x0, x1, 15) TF_ROUND(x0, x1, 26) TF_ROUND(x0, x1, 6)
  x0 += k0; x1 += k1 + 3u;
  TF_ROUND(x0, x1, 17) TF_ROUND(x0, x1, 29) TF_ROUND(x0, x1, 16) TF_ROUND(x0, x1, 24)
  x0 += k1; x1 += k2 + 4u;
  TF_ROUND(x0, x1, 13) TF_ROUND(x0, x1, 15) TF_ROUND(x0, x1, 26) TF_ROUND(x0, x1, 6)
  x0 += k2; x1 += k0 + 5u;
  return x0 ^ x1;
}

__global__ void final_kernel(const float* __restrict__ h,
                             const float* __restrict__ b4,
                             const float* __restrict__ W5,
                             const float* __restrict__ b5,
                             float* __restrict__ out, int n) {
  __shared__ float w5s[640];
  __shared__ float b5s[16];
  for (int i = threadIdx.x; i < 640; i += blockDim.x) w5s[i] = W5[i];
  if (threadIdx.x < 10) b5s[threadIdx.x] = b5[threadIdx.x];
  __syncthreads();
  int gw = (blockIdx.x * blockDim.x + threadIdx.x) >> 5;
  int lane = threadIdx.x & 31;
  if (gw >= n) return;
  int i = gw;
  float v0 = h[i * 64 + lane] + b4[lane];
  v0 = (v0 > 0.f) ? v0 : 0.01f * v0;
  float v1 = h[i * 64 + lane + 32] + b4[lane + 32];
  v1 = (v1 > 0.f) ? v1 : 0.01f * v1;
  uint32_t bits0 = threefry_bits((uint32_t)(i * 64 + lane));
  uint32_t bits1 = threefry_bits((uint32_t)(i * 64 + lane + 32));
  v0 = (bits0 & 0x80000000u) ? 0.f : v0 * 2.f;
  v1 = (bits1 & 0x80000000u) ? 0.f : v1 * 2.f;
#pragma unroll
  for (int j = 0; j < 10; ++j) {
    float p = v0 * w5s[lane * 10 + j] + v1 * w5s[(lane + 32) * 10 + j];
#pragma unroll
    for (int off = 16; off; off >>= 1)
      p += __shfl_xor_sync(0xffffffffu, p, off);
    if (lane == 0) out[i * 10 + j] = p + b5s[j];
  }
}

// ------------------------------ launch -------------------------------------
extern "C" void kernel_launch(void* const* d_in, const int* in_sizes, int n_in,
                              void* d_out, int out_size) {
  const float* x = (const float*)d_in[0];
  const int* ei = (const int*)d_in[1];   // int32
  const float* W1 = (const float*)d_in[2];
  const float* b1 = (const float*)d_in[3];
  const float* W2 = (const float*)d_in[4];
  const float* b2 = (const float*)d_in[5];
  const float* W3 = (const float*)d_in[6];
  const float* b3 = (const float*)d_in[7];
  const float* W4 = (const float*)d_in[8];
  const float* b4 = (const float*)d_in[9];
  const float* W5 = (const float*)d_in[10];
  const float* b5 = (const float*)d_in[11];
  const int N = in_sizes[0] / 256;
  const int E = in_sizes[1] / 2;
  const int* src = ei;
  const int* dstp = ei + E;

  float* tmp = nullptr; float* y = nullptr;
  __nv_bfloat16 *ah = nullptr, *al = nullptr, *wh = nullptr, *wl = nullptr;
  cudaGetSymbolAddress((void**)&tmp, g_tmp);
  cudaGetSymbolAddress((void**)&y, g_y);
  cudaGetSymbolAddress((void**)&ah, g_ah);
  cudaGetSymbolAddress((void**)&al, g_al);
  cudaGetSymbolAddress((void**)&wh, g_wh);
  cudaGetSymbolAddress((void**)&wl, g_wl);

  constexpr int SM_128 = 2 * (20480 + 2 * 128 * 80);  // 81920
  constexpr int SM_64  = 2 * (20480 + 2 * 64 * 80);   // 61440
  cudaFuncSetAttribute(gemm_bf16_kernel<128>,
                       cudaFuncAttributeMaxDynamicSharedMemorySize, SM_128);
  cudaFuncSetAttribute(gemm_bf16_kernel<64>,
                       cudaFuncAttributeMaxDynamicSharedMemorySize, SM_64);

  // operand splits
  split_x_kernel<<<(N * 256 + 255) / 256, 256>>>(x, ah, al, N * 256);
  split_wt_all_kernel<<<(172032 + 255) / 256, 256>>>(W1, W2, W3, W4, wh, wl);

  // normalization + CSR build
  deg_init_kernel<<<(N + 255) / 256, 256>>>(N);
  deg_count_kernel<<<(E + 255) / 256, 256>>>(dstp, E);
  dinv_kernel<<<(N + 255) / 256, 256>>>(N);
  int nblk = (N + SCAN_BLK - 1) / SCAN_BLK;
  scan1_kernel<<<nblk, SCAN_BLK>>>(N);
  scan2_kernel<<<1, 64>>>(nblk);
  scan3_kernel<<<(N + 256) / 256, 256>>>(N, E);
  fill_kernel<<<(E + 255) / 256, 256>>>(src, dstp, E);

  const int MB = (N + 127) / 128;       // 391
  const int GW = (N * 32 + 255) / 256;  // warp per row

  // L1: 256->256
  gemm_bf16_kernel<128><<<dim3(MB, 2), 256, SM_128>>>(
      ah, al, wh, wl, tmp, N, 256, 256);
  gather_split_kernel<256><<<GW, 256>>>(tmp, b1, ah, al, N);

  // L2: 256->256
  gemm_bf16_kernel<128><<<dim3(MB, 2), 256, SM_128>>>(
      ah, al, wh + 65536, wl + 65536, tmp, N, 256, 256);
  gather_split_kernel<256><<<GW, 256>>>(tmp, b2, ah, al, N);

  // L3: 256->128
  gemm_bf16_kernel<128><<<dim3(MB, 1), 256, SM_128>>>(
      ah, al, wh + 131072, wl + 131072, tmp, N, 256, 128);
  gather_split_kernel<128><<<GW, 256>>>(tmp, b3, ah, al, N);

  // L4: 128->64
  gemm_bf16_kernel<64><<<dim3(MB, 1), 256, SM_64>>>(
      ah, al, wh + 163840, wl + 163840, tmp, N, 128, 64);
  gather_raw64_kernel<<<GW, 256>>>(tmp, y, N);

  // bias4 + lrelu + dropout + dense 64->10
  final_kernel<<<(N * 32 + 255) / 256, 256>>>(y, b4, W5, b5, (float*)d_out, N);
}

// round 13
// speedup vs baseline: 4.2275x; 1.0173x over previous
#include <cuda_runtime.h>
#include <cuda_bf16.h>
#include <stdint.h>

// ---------------------------------------------------------------------------
// ShallowGCNet: 4x GCNConv(lrelu) + dropout + dense
// N=50000, E=800000, features 256->256->256->128->64->10
// GEMM: bf16 double-split (3 products) m16n8k16 mma.sync + ldmatrix,
// cp.async 2-stage pipeline, 2 CTAs/SM. Aggregation: CSR gather (L2-bound).
// L4 gather fused with bias+lrelu+dropout+dense epilogue.
// ---------------------------------------------------------------------------

__device__ float g_tmp[50000 * 256];   // GEMM output / gather input
__device__ __nv_bfloat16 g_ah[50000 * 256];  // A hi plane
__device__ __nv_bfloat16 g_al[50000 * 256];  // A lo plane
__device__ __nv_bfloat16 g_wh[172032];       // W^T hi  [Fout][K]
__device__ __nv_bfloat16 g_wl[172032];       // W^T lo
// offsets: w1=0 w2=65536 w3=131072 w4=163840
__device__ float g_dinv[50000];
__device__ int   g_deg[50000];
__device__ int   g_off[50001];
__device__ int   g_bsum[64];
__device__ int   g_fill[50000];
__device__ int   g_csr_src[800000];
__device__ float g_csr_w[800000];

// ------------------------------ degree ------------------------------------
__global__ void deg_init_kernel(int n) {
  int i = blockIdx.x * blockDim.x + threadIdx.x;
  if (i < n) { g_deg[i] = 0; g_fill[i] = 0; }
}
// 4 edges per thread via int4 (E % 4 == 0, 16B-aligned)
__global__ void deg_count_kernel(const int* __restrict__ dst, int E4) {
  int e = blockIdx.x * blockDim.x + threadIdx.x;
  if (e >= E4) return;
  int4 d = ((const int4*)dst)[e];
  atomicAdd(&g_deg[d.x], 1);
  atomicAdd(&g_deg[d.y], 1);
  atomicAdd(&g_deg[d.z], 1);
  atomicAdd(&g_deg[d.w], 1);
}

// ------------------------------ CSR build ----------------------------------
#define SCAN_BLK 1024
__global__ void scan1_kernel(int n) {   // also computes dinv
  __shared__ int sh[SCAN_BLK];
  int i = blockIdx.x * SCAN_BLK + threadIdx.x;
  int v = (i < n) ? g_deg[i] : 0;
  if (i < n) g_dinv[i] = 1.0f / sqrtf((float)(v + 1));  // +1 self-loop
  sh[threadIdx.x] = v;
  __syncthreads();
#pragma unroll
  for (int d = 1; d < SCAN_BLK; d <<= 1) {
    int t = (threadIdx.x >= d) ? sh[threadIdx.x - d] : 0;
    __syncthreads();
    sh[threadIdx.x] += t;
    __syncthreads();
  }
  if (i < n) g_off[i] = sh[threadIdx.x] - v;
  if (threadIdx.x == SCAN_BLK - 1) g_bsum[blockIdx.x] = sh[threadIdx.x];
}
__global__ void scan2_kernel(int nb) {
  __shared__ int sh[64];
  int v = (threadIdx.x < nb) ? g_bsum[threadIdx.x] : 0;
  sh[threadIdx.x] = v;
  __syncthreads();
#pragma unroll
  for (int d = 1; d < 64; d <<= 1) {
    int t = (threadIdx.x >= d) ? sh[threadIdx.x - d] : 0;
    __syncthreads();
    sh[threadIdx.x] += t;
    __syncthreads();
  }
  if (threadIdx.x < nb) g_bsum[threadIdx.x] = sh[threadIdx.x] - v;
}
__global__ void scan3_kernel(int n, int E) {
  int i = blockIdx.x * blockDim.x + threadIdx.x;
  if (i < n) g_off[i] += g_bsum[i >> 10];
  if (i == n) g_off[n] = E;
}
__global__ void fill_kernel(const int* __restrict__ src,
                            const int* __restrict__ dst, int E) {
  int e = blockIdx.x * blockDim.x + threadIdx.x;
  if (e >= E) return;
  int s = src[e], d = dst[e];
  int pos = g_off[d] + atomicAdd(&g_fill[d], 1);
  g_csr_src[pos] = s;
  g_csr_w[pos] = g_dinv[s];
}

// ------------------------- bf16 split helpers -------------------------------
__device__ __forceinline__ uint32_t pack_bf2(__nv_bfloat16 a, __nv_bfloat16 b) {
  return (uint32_t)__bfloat16_as_ushort(a) |
         ((uint32_t)__bfloat16_as_ushort(b) << 16);
}

__global__ void split_x_kernel(const float* __restrict__ x,
                               __nv_bfloat16* __restrict__ h,
                               __nv_bfloat16* __restrict__ l, int n) {
  int i = blockIdx.x * blockDim.x + threadIdx.x;
  if (i >= n) return;
  float v = x[i];
  __nv_bfloat16 hh = __float2bfloat16(v);
  h[i] = hh;
  l[i] = __float2bfloat16(v - __bfloat162float(hh));
}

// All four W matrices -> transposed hi/lo planes, single launch.
__global__ void split_wt_all_kernel(const float* __restrict__ W1,
                                    const float* __restrict__ W2,
                                    const float* __restrict__ W3,
                                    const float* __restrict__ W4,
                                    __nv_bfloat16* __restrict__ h,
                                    __nv_bfloat16* __restrict__ l) {
  int i = blockIdx.x * blockDim.x + threadIdx.x;
  if (i >= 172032) return;
  const float* W; int K, F, base, i0;
  if (i < 65536)        { W = W1; K = 256; F = 256; base = 0;      i0 = i; }
  else if (i < 131072)  { W = W2; K = 256; F = 256; base = 65536;  i0 = i - 65536; }
  else if (i < 163840)  { W = W3; K = 256; F = 128; base = 131072; i0 = i - 131072; }
  else                  { W = W4; K = 128; F = 64;  base = 163840; i0 = i - 163840; }
  int k = i0 / F, nn = i0 % F;
  float v = W[i0];
  __nv_bfloat16 hh = __float2bfloat16(v);
  h[base + nn * K + k] = hh;
  l[base + nn * K + k] = __float2bfloat16(v - __bfloat162float(hh));
}

// ------------------------ bf16 mma GEMM ------------------------------------
__device__ __forceinline__ void cp16(uint32_t dst, const void* src) {
  asm volatile("cp.async.ca.shared.global [%0], [%1], 16;"
               :: "r"(dst), "l"(src));
}
__device__ __forceinline__ void cp_commit() {
  asm volatile("cp.async.commit_group;");
}
template<int n> __device__ __forceinline__ void cp_wait() {
  asm volatile("cp.async.wait_group %0;" :: "n"(n));
}

#define MMA_BF16(c, a, b0, b1)                                         \
  asm volatile(                                                        \
      "mma.sync.aligned.m16n8k16.row.col.f32.bf16.bf16.f32 "           \
      "{%0,%1,%2,%3}, {%4,%5,%6,%7}, {%8,%9}, {%0,%1,%2,%3};"          \
      : "+f"((c)[0]), "+f"((c)[1]), "+f"((c)[2]), "+f"((c)[3])         \
      : "r"((a)[0]), "r"((a)[1]), "r"((a)[2]), "r"((a)[3]),            \
        "r"(b0), "r"(b1))

#define LDM4(r, addr)                                                  \
  asm volatile("ldmatrix.sync.aligned.m8n8.x4.shared.b16 "             \
               "{%0,%1,%2,%3}, [%4];"                                  \
               : "=r"((r)[0]), "=r"((r)[1]), "=r"((r)[2]), "=r"((r)[3])\
               : "r"(addr))

template<int BN>
__global__ void __launch_bounds__(256, 2) gemm_bf16_kernel(
    const __nv_bfloat16* __restrict__ Ah, const __nv_bfloat16* __restrict__ Al,
    const __nv_bfloat16* __restrict__ Bh, const __nv_bfloat16* __restrict__ Bl,
    float* __restrict__ C, int N, int K, int Fout) {
  constexpr int SB = BN * 80;
  constexpr int ST = 20480 + 2 * SB;
  constexpr int NA = BN / 16;
  constexpr int NP = NA / 2;
  extern __shared__ char smc[];
  const uint32_t smu = (uint32_t)__cvta_generic_to_shared(smc);

  const int tid = threadIdx.x;
  const int wid = tid >> 5, lane = tid & 31;
  const int wm = wid & 3, wn = wid >> 2;
  const int row0 = blockIdx.x * 128;
  const int col0 = blockIdx.y * BN;
  const int NIT = K >> 5;

  const uint32_t a_rel =
      (uint32_t)(wm * 32 + (lane & 15)) * 80u + (uint32_t)(lane >> 4) * 16u;
  const uint32_t b_rel = 20480u +
      (uint32_t)(wn * (BN / 2) + (lane & 7) + ((lane >> 4) << 3)) * 80u +
      (uint32_t)((lane >> 3) & 1) * 16u;

  float c[2][NA][4] = {};

  auto load_stage = [&](int s, int k0) {
    uint32_t sb = smu + (uint32_t)s * ST;
    int r = tid >> 2, q = tid & 3;
#pragma unroll
    for (int p = 0; p < 2; ++p) {
      int rr = r + p * 64;
      int grow = row0 + rr; if (grow >= N) grow = N - 1;
      cp16(sb + rr * 80 + q * 16, Ah + (size_t)grow * K + k0 + q * 8);
      cp16(sb + 10240 + rr * 80 + q * 16, Al + (size_t)grow * K + k0 + q * 8);
    }
#pragma unroll
    for (int p = 0; p < BN / 64; ++p) {
      int rr = r + p * 64;
      int gc = col0 + rr;
      cp16(sb + 20480 + rr * 80 + q * 16, Bh + (size_t)gc * K + k0 + q * 8);
      cp16(sb + 20480 + SB + rr * 80 + q * 16, Bl + (size_t)gc * K + k0 + q * 8);
    }
  };

  load_stage(0, 0);
  cp_commit();
  for (int it = 0; it < NIT; ++it) {
    if (it + 1 < NIT) {
      load_stage((it + 1) & 1, (it + 1) * 32);
      cp_commit();
      cp_wait<1>();
    } else {
      cp_wait<0>();
    }
    __syncthreads();
    uint32_t sbu = smu + (uint32_t)(it & 1) * ST;
#pragma unroll
    for (int ka = 0; ka < 2; ++ka) {
      uint32_t ah[2][4], al[2][4];
#pragma unroll
      for (int ma = 0; ma < 2; ++ma) {
        uint32_t base = sbu + a_rel + (uint32_t)ma * 1280u + (uint32_t)ka * 32u;
        LDM4(ah[ma], base);
        LDM4(al[ma], base + 10240u);
      }
#pragma unroll
      for (int p = 0; p < NP; ++p) {
        uint32_t base = sbu + b_rel + (uint32_t)p * (16u * 80u) + (uint32_t)ka * 32u;
        uint32_t rb[4], rl[4];
        LDM4(rb, base);
        LDM4(rl, base + (uint32_t)SB);
#pragma unroll
        for (int ma = 0; ma < 2; ++ma) {
          MMA_BF16(c[ma][2 * p],     ah[ma], rb[0], rb[1]);
          MMA_BF16(c[ma][2 * p],     al[ma], rb[0], rb[1]);
          MMA_BF16(c[ma][2 * p],     ah[ma], rl[0], rl[1]);
          MMA_BF16(c[ma][2 * p + 1], ah[ma], rb[2], rb[3]);
          MMA_BF16(c[ma][2 * p + 1], al[ma], rb[2], rb[3]);
          MMA_BF16(c[ma][2 * p + 1], ah[ma], rl[2], rl[3]);
        }
      }
    }
    __syncthreads();
  }

  const int gq = lane >> 2, tq = lane & 3;
#pragma unroll
  for (int ma = 0; ma < 2; ++ma) {
    int row = row0 + wm * 32 + ma * 16 + gq;
#pragma unroll
    for (int na = 0; na < NA; ++na) {
      int col = col0 + wn * (BN / 2) + na * 8 + tq * 2;
      if (row < N)
        *(float2*)(C + (size_t)row * Fout + col) =
            make_float2(c[ma][na][0], c[ma][na][1]);
      if (row + 8 < N)
        *(float2*)(C + (size_t)(row + 8) * Fout + col) =
            make_float2(c[ma][na][2], c[ma][na][3]);
    }
  }
}

// -------------- CSR gather + fused bias/lrelu/bf16-split --------------------
template<int F>
__global__ void gather_split_kernel(const float* __restrict__ tmp,
                                    const float* __restrict__ bias,
                                    __nv_bfloat16* __restrict__ oh,
                                    __nv_bfloat16* __restrict__ ol, int n) {
  int w = (blockIdx.x * blockDim.x + threadIdx.x) >> 5;
  int lane = threadIdx.x & 31;
  if (w >= n) return;
  int beg = g_off[w], end = g_off[w + 1];
  float dr = g_dinv[w];
  constexpr int NV = F / 128;
  float4 acc[NV];
  const float4* self = (const float4*)(tmp + (size_t)w * F);
#pragma unroll
  for (int v = 0; v < NV; ++v) {
    float4 x = self[lane + 32 * v];
    acc[v] = make_float4(x.x * dr, x.y * dr, x.z * dr, x.w * dr);
  }
  for (int e0 = beg; e0 < end; e0 += 32) {
    int ne = min(32, end - e0);
    int s = 0; float ww = 0.f;
    if (lane < ne) { s = g_csr_src[e0 + lane]; ww = g_csr_w[e0 + lane]; }
    for (int j = 0; j < ne; ++j) {
      int sj = __shfl_sync(0xffffffffu, s, j);
      float wj = __shfl_sync(0xffffffffu, ww, j);
      const float4* sr = (const float4*)(tmp + (size_t)sj * F);
#pragma unroll
      for (int v = 0; v < NV; ++v) {
        float4 x = sr[lane + 32 * v];
        acc[v].x += wj * x.x; acc[v].y += wj * x.y;
        acc[v].z += wj * x.z; acc[v].w += wj * x.w;
      }
    }
  }
  uint32_t* ph = (uint32_t*)(oh + (size_t)w * F);
  uint32_t* pl = (uint32_t*)(ol + (size_t)w * F);
#pragma unroll
  for (int v = 0; v < NV; ++v) {
    int cb = lane + 32 * v;
    float4 b = *(const float4*)(bias + 4 * cb);
    float4 z = make_float4(acc[v].x * dr + b.x, acc[v].y * dr + b.y,
                           acc[v].z * dr + b.z, acc[v].w * dr + b.w);
    z.x = z.x > 0.f ? z.x : 0.01f * z.x;
    z.y = z.y > 0.f ? z.y : 0.01f * z.y;
    z.z = z.z > 0.f ? z.z : 0.01f * z.z;
    z.w = z.w > 0.f ? z.w : 0.01f * z.w;
    __nv_bfloat16 hx = __float2bfloat16(z.x), hy = __float2bfloat16(z.y);
    __nv_bfloat16 hz = __float2bfloat16(z.z), hw = __float2bfloat16(z.w);
    ph[2 * cb + 0] = pack_bf2(hx, hy);
    ph[2 * cb + 1] = pack_bf2(hz, hw);
    pl[2 * cb + 0] = pack_bf2(__float2bfloat16(z.x - __bfloat162float(hx)),
                              __float2bfloat16(z.y - __bfloat162float(hy)));
    pl[2 * cb + 1] = pack_bf2(__float2bfloat16(z.z - __bfloat162float(hz)),
                              __float2bfloat16(z.w - __bfloat162float(hw)));
  }
}

// ------------------- dropout (JAX threefry) -------------------------
#define TF_ROUND(x0, x1, r)                         \
  { x0 += x1; x1 = (x1 << (r)) | (x1 >> (32 - (r))); x1 ^= x0; }

__device__ __forceinline__ uint32_t threefry_bits(uint32_t idx) {
  const uint32_t k0 = 0u, k1 = 42u;
  const uint32_t k2 = 0x1BD11BDAu ^ k0 ^ k1;
  uint32_t x0 = 0u, x1 = idx;
  x0 += k0; x1 += k1;
  TF_ROUND(x0, x1, 13) TF_ROUND(x0, x1, 15) TF_ROUND(x0, x1, 26) TF_ROUND(x0, x1, 6)
  x0 += k1; x1 += k2 + 1u;
  TF_ROUND(x0, x1, 17) TF_ROUND(x0, x1, 29) TF_ROUND(x0, x1, 16) TF_ROUND(x0, x1, 24)
  x0 += k2; x1 += k0 + 2u;
  TF_ROUND(x0, x1, 13) TF_ROUND(x0, x1, 15) TF_ROUND(x0, x1, 26) TF_ROUND(x0, x1, 6)
  x0 += k0; x1 += k1 + 3u;
  TF_ROUND(x0, x1, 17) TF_ROUND(x0, x1, 29) TF_ROUND(x0, x1, 16) TF_ROUND(x0, x1, 24)
  x0 += k1; x1 += k2 + 4u;
  TF_ROUND(x0, x1, 13) TF_ROUND(x0, x1, 15) TF_ROUND(x0, x1, 26) TF_ROUND(x0, x1, 6)
  x0 += k2; x1 += k0 + 5u;
  return x0 ^ x1;
}

// L4 gather fused with bias4 + lrelu + dropout + dense 64->10.
// Warp per dst row; lane holds features (2l, 2l+1).
__global__ void gather_final_kernel(const float* __restrict__ tmp,
                                    const float* __restrict__ b4,
                                    const float* __restrict__ W5,
                                    const float* __restrict__ b5,
                                    float* __restrict__ out, int n) {
  __shared__ float w5s[640];
  __shared__ float b5s[16];
  for (int i = threadIdx.x; i < 640; i += blockDim.x) w5s[i] = W5[i];
  if (threadIdx.x < 10) b5s[threadIdx.x] = b5[threadIdx.x];
  __syncthreads();

  int w = (blockIdx.x * blockDim.x + threadIdx.x) >> 5;
  int lane = threadIdx.x & 31;
  if (w >= n) return;
  int beg = g_off[w], end = g_off[w + 1];
  float dr = g_dinv[w];
  float2 acc;
  {
    float2 x = ((const float2*)(tmp + (size_t)w * 64))[lane];
    acc = make_float2(x.x * dr, x.y * dr);
  }
  for (int e0 = beg; e0 < end; e0 += 32) {
    int ne = min(32, end - e0);
    int s = 0; float ww = 0.f;
    if (lane < ne) { s = g_csr_src[e0 + lane]; ww = g_csr_w[e0 + lane]; }
    for (int j = 0; j < ne; ++j) {
      int sj = __shfl_sync(0xffffffffu, s, j);
      float wj = __shfl_sync(0xffffffffu, ww, j);
      float2 x = ((const float2*)(tmp + (size_t)sj * 64))[lane];
      acc.x += wj * x.x; acc.y += wj * x.y;
    }
  }
  // epilogue: bias + lrelu + dropout + dense
  int f0 = 2 * lane, f1 = 2 * lane + 1;
  float v0 = acc.x * dr + b4[f0];
  v0 = (v0 > 0.f) ? v0 : 0.01f * v0;
  float v1 = acc.y * dr + b4[f1];
  v1 = (v1 > 0.f) ? v1 : 0.01f * v1;
  uint32_t bits0 = threefry_bits((uint32_t)(w * 64 + f0));
  uint32_t bits1 = threefry_bits((uint32_t)(w * 64 + f1));
  v0 = (bits0 & 0x80000000u) ? 0.f : v0 * 2.f;
  v1 = (bits1 & 0x80000000u) ? 0.f : v1 * 2.f;
#pragma unroll
  for (int j = 0; j < 10; ++j) {
    float p = v0 * w5s[f0 * 10 + j] + v1 * w5s[f1 * 10 + j];
#pragma unroll
    for (int off = 16; off; off >>= 1)
      p += __shfl_xor_sync(0xffffffffu, p, off);
    if (lane == 0) out[w * 10 + j] = p + b5s[j];
  }
}

// ------------------------------ launch -------------------------------------
extern "C" void kernel_launch(void* const* d_in, const int* in_sizes, int n_in,
                              void* d_out, int out_size) {
  const float* x = (const float*)d_in[0];
  const int* ei = (const int*)d_in[1];   // int32
  const float* W1 = (const float*)d_in[2];
  const float* b1 = (const float*)d_in[3];
  const float* W2 = (const float*)d_in[4];
  const float* b2 = (const float*)d_in[5];
  const float* W3 = (const float*)d_in[6];
  const float* b3 = (const float*)d_in[7];
  const float* W4 = (const float*)d_in[8];
  const float* b4 = (const float*)d_in[9];
  const float* W5 = (const float*)d_in[10];
  const float* b5 = (const float*)d_in[11];
  const int N = in_sizes[0] / 256;
  const int E = in_sizes[1] / 2;
  const int* src = ei;
  const int* dstp = ei + E;

  float* tmp = nullptr;
  __nv_bfloat16 *ah = nullptr, *al = nullptr, *wh = nullptr, *wl = nullptr;
  cudaGetSymbolAddress((void**)&tmp, g_tmp);
  cudaGetSymbolAddress((void**)&ah, g_ah);
  cudaGetSymbolAddress((void**)&al, g_al);
  cudaGetSymbolAddress((void**)&wh, g_wh);
  cudaGetSymbolAddress((void**)&wl, g_wl);

  constexpr int SM_128 = 2 * (20480 + 2 * 128 * 80);  // 81920
  constexpr int SM_64  = 2 * (20480 + 2 * 64 * 80);   // 61440
  cudaFuncSetAttribute(gemm_bf16_kernel<128>,
                       cudaFuncAttributeMaxDynamicSharedMemorySize, SM_128);
  cudaFuncSetAttribute(gemm_bf16_kernel<64>,
                       cudaFuncAttributeMaxDynamicSharedMemorySize, SM_64);

  // operand splits
  split_x_kernel<<<(N * 256 + 255) / 256, 256>>>(x, ah, al, N * 256);
  split_wt_all_kernel<<<(172032 + 255) / 256, 256>>>(W1, W2, W3, W4, wh, wl);

  // normalization + CSR build
  deg_init_kernel<<<(N + 255) / 256, 256>>>(N);
  deg_count_kernel<<<(E / 4 + 255) / 256, 256>>>(dstp, E / 4);
  int nblk = (N + SCAN_BLK - 1) / SCAN_BLK;
  scan1_kernel<<<nblk, SCAN_BLK>>>(N);
  scan2_kernel<<<1, 64>>>(nblk);
  scan3_kernel<<<(N + 256) / 256, 256>>>(N, E);
  fill_kernel<<<(E + 255) / 256, 256>>>(src, dstp, E);

  const int MB = (N + 127) / 128;       // 391
  const int GW = (N * 32 + 255) / 256;  // warp per row

  // L1: 256->256
  gemm_bf16_kernel<128><<<dim3(MB, 2), 256, SM_128>>>(
      ah, al, wh, wl, tmp, N, 256, 256);
  gather_split_kernel<256><<<GW, 256>>>(tmp, b1, ah, al, N);

  // L2: 256->256
  gemm_bf16_kernel<128><<<dim3(MB, 2), 256, SM_128>>>(
      ah, al, wh + 65536, wl + 65536, tmp, N, 256, 256);
  gather_split_kernel<256><<<GW, 256>>>(tmp, b2, ah, al, N);

  // L3: 256->128
  gemm_bf16_kernel<128><<<dim3(MB, 1), 256, SM_128>>>(
      ah, al, wh + 131072, wl + 131072, tmp, N, 256, 128);
  gather_split_kernel<128><<<GW, 256>>>(tmp, b3, ah, al, N);

  // L4: 128->64, gather fused with final epilogue
  gemm_bf16_kernel<64><<<dim3(MB, 1), 256, SM_64>>>(
      ah, al, wh + 163840, wl + 163840, tmp, N, 128, 64);
  gather_final_kernel<<<GW, 256>>>(tmp, b4, W5, b5, (float*)d_out, N);
}

// round 14
// speedup vs baseline: 4.3888x; 1.0381x over previous
#include <cuda_runtime.h>
#include <cuda_bf16.h>
#include <stdint.h>

// ---------------------------------------------------------------------------
// ShallowGCNet: 4x GCNConv(lrelu) + dropout + dense
// N=50000, E=800000, features 256->256->256->128->64->10
// GEMM: bf16 double-split (3 products) m16n8k16 mma.sync + ldmatrix,
// cp.async 2-stage pipeline, 2 CTAs/SM. Aggregation: CSR gather (L2-bound).
// CSR build runs on a forked side stream, overlapped with splits + L1 GEMM.
// ---------------------------------------------------------------------------

__device__ float g_tmp[50000 * 256];   // GEMM output / gather input
__device__ __nv_bfloat16 g_ah[50000 * 256];  // A hi plane
__device__ __nv_bfloat16 g_al[50000 * 256];  // A lo plane
__device__ __nv_bfloat16 g_wh[172032];       // W^T hi  [Fout][K]
__device__ __nv_bfloat16 g_wl[172032];       // W^T lo
// offsets: w1=0 w2=65536 w3=131072 w4=163840
__device__ float g_dinv[50000];
__device__ int   g_deg[50000];
__device__ int   g_off[50001];
__device__ int   g_bsum[64];
__device__ int   g_fill[50000];
__device__ int   g_csr_src[800000];
__device__ float g_csr_w[800000];

// ------------------------------ degree ------------------------------------
__global__ void deg_init_kernel(int n) {
  int i = blockIdx.x * blockDim.x + threadIdx.x;
  if (i < n) { g_deg[i] = 0; g_fill[i] = 0; }
}
// 1 edge/thread: atomics gain nothing from per-thread MLP (R13: int4 regressed)
__global__ void deg_count_kernel(const int* __restrict__ dst, int E) {
  int e = blockIdx.x * blockDim.x + threadIdx.x;
  if (e < E) atomicAdd(&g_deg[dst[e]], 1);
}

// ------------------------------ CSR build ----------------------------------
#define SCAN_BLK 1024
__global__ void scan1_kernel(int n) {   // also computes dinv
  __shared__ int sh[SCAN_BLK];
  int i = blockIdx.x * SCAN_BLK + threadIdx.x;
  int v = (i < n) ? g_deg[i] : 0;
  if (i < n) g_dinv[i] = 1.0f / sqrtf((float)(v + 1));  // +1 self-loop
  sh[threadIdx.x] = v;
  __syncthreads();
#pragma unroll
  for (int d = 1; d < SCAN_BLK; d <<= 1) {
    int t = (threadIdx.x >= d) ? sh[threadIdx.x - d] : 0;
    __syncthreads();
    sh[threadIdx.x] += t;
    __syncthreads();
  }
  if (i < n) g_off[i] = sh[threadIdx.x] - v;
  if (threadIdx.x == SCAN_BLK - 1) g_bsum[blockIdx.x] = sh[threadIdx.x];
}
__global__ void scan2_kernel(int nb) {
  __shared__ int sh[64];
  int v = (threadIdx.x < nb) ? g_bsum[threadIdx.x] : 0;
  sh[threadIdx.x] = v;
  __syncthreads();
#pragma unroll
  for (int d = 1; d < 64; d <<= 1) {
    int t = (threadIdx.x >= d) ? sh[threadIdx.x - d] : 0;
    __syncthreads();
    sh[threadIdx.x] += t;
    __syncthreads();
  }
  if (threadIdx.x < nb) g_bsum[threadIdx.x] = sh[threadIdx.x] - v;
}
__global__ void scan3_kernel(int n, int E) {
  int i = blockIdx.x * blockDim.x + threadIdx.x;
  if (i < n) g_off[i] += g_bsum[i >> 10];
  if (i == n) g_off[n] = E;
}
__global__ void fill_kernel(const int* __restrict__ src,
                            const int* __restrict__ dst, int E) {
  int e = blockIdx.x * blockDim.x + threadIdx.x;
  if (e >= E) return;
  int s = src[e], d = dst[e];
  int pos = g_off[d] + atomicAdd(&g_fill[d], 1);
  g_csr_src[pos] = s;
  g_csr_w[pos] = g_dinv[s];
}

// ------------------------- bf16 split helpers -------------------------------
__device__ __forceinline__ uint32_t pack_bf2(__nv_bfloat16 a, __nv_bfloat16 b) {
  return (uint32_t)__bfloat16_as_ushort(a) |
         ((uint32_t)__bfloat16_as_ushort(b) << 16);
}

__global__ void split_x_kernel(const float* __restrict__ x,
                               __nv_bfloat16* __restrict__ h,
                               __nv_bfloat16* __restrict__ l, int n) {
  int i = blockIdx.x * blockDim.x + threadIdx.x;
  if (i >= n) return;
  float v = x[i];
  __nv_bfloat16 hh = __float2bfloat16(v);
  h[i] = hh;
  l[i] = __float2bfloat16(v - __bfloat162float(hh));
}

// All four W matrices -> transposed hi/lo planes, single launch.
__global__ void split_wt_all_kernel(const float* __restrict__ W1,
                                    const float* __restrict__ W2,
                                    const float* __restrict__ W3,
                                    const float* __restrict__ W4,
                                    __nv_bfloat16* __restrict__ h,
                                    __nv_bfloat16* __restrict__ l) {
  int i = blockIdx.x * blockDim.x + threadIdx.x;
  if (i >= 172032) return;
  const float* W; int K, F, base, i0;
  if (i < 65536)        { W = W1; K = 256; F = 256; base = 0;      i0 = i; }
  else if (i < 131072)  { W = W2; K = 256; F = 256; base = 65536;  i0 = i - 65536; }
  else if (i < 163840)  { W = W3; K = 256; F = 128; base = 131072; i0 = i - 131072; }
  else                  { W = W4; K = 128; F = 64;  base = 163840; i0 = i - 163840; }
  int k = i0 / F, nn = i0 % F;
  float v = W[i0];
  __nv_bfloat16 hh = __float2bfloat16(v);
  h[base + nn * K + k] = hh;
  l[base + nn * K + k] = __float2bfloat16(v - __bfloat162float(hh));
}

// ------------------------ bf16 mma GEMM ------------------------------------
__device__ __forceinline__ void cp16(uint32_t dst, const void* src) {
  asm volatile("cp.async.ca.shared.global [%0], [%1], 16;"
               :: "r"(dst), "l"(src));
}
__device__ __forceinline__ void cp_commit() {
  asm volatile("cp.async.commit_group;");
}
template<int n> __device__ __forceinline__ void cp_wait() {
  asm volatile("cp.async.wait_group %0;" :: "n"(n));
}

#define MMA_BF16(c, a, b0, b1)                                         \
  asm volatile(                                                        \
      "mma.sync.aligned.m16n8k16.row.col.f32.bf16.bf16.f32 "           \
      "{%0,%1,%2,%3}, {%4,%5,%6,%7}, {%8,%9}, {%0,%1,%2,%3};"          \
      : "+f"((c)[0]), "+f"((c)[1]), "+f"((c)[2]), "+f"((c)[3])         \
      : "r"((a)[0]), "r"((a)[1]), "r"((a)[2]), "r"((a)[3]),            \
        "r"(b0), "r"(b1))

#define LDM4(r, addr)                                                  \
  asm volatile("ldmatrix.sync.aligned.m8n8.x4.shared.b16 "             \
               "{%0,%1,%2,%3}, [%4];"                                  \
               : "=r"((r)[0]), "=r"((r)[1]), "=r"((r)[2]), "=r"((r)[3])\
               : "r"(addr))

template<int BN>
__global__ void __launch_bounds__(256, 2) gemm_bf16_kernel(
    const __nv_bfloat16* __restrict__ Ah, const __nv_bfloat16* __restrict__ Al,
    const __nv_bfloat16* __restrict__ Bh, const __nv_bfloat16* __restrict__ Bl,
    float* __restrict__ C, int N, int K, int Fout) {
  constexpr int SB = BN * 80;
  constexpr int ST = 20480 + 2 * SB;
  constexpr int NA = BN / 16;
  constexpr int NP = NA / 2;
  extern __shared__ char smc[];
  const uint32_t smu = (uint32_t)__cvta_generic_to_shared(smc);

  const int tid = threadIdx.x;
  const int wid = tid >> 5, lane = tid & 31;
  const int wm = wid & 3, wn = wid >> 2;
  const int row0 = blockIdx.x * 128;
  const int col0 = blockIdx.y * BN;
  const int NIT = K >> 5;

  const uint32_t a_rel =
      (uint32_t)(wm * 32 + (lane & 15)) * 80u + (uint32_t)(lane >> 4) * 16u;
  const uint32_t b_rel = 20480u +
      (uint32_t)(wn * (BN / 2) + (lane & 7) + ((lane >> 4) << 3)) * 80u +
      (uint32_t)((lane >> 3) & 1) * 16u;

  float c[2][NA][4] = {};

  auto load_stage = [&](int s, int k0) {
    uint32_t sb = smu + (uint32_t)s * ST;
    int r = tid >> 2, q = tid & 3;
#pragma unroll
    for (int p = 0; p < 2; ++p) {
      int rr = r + p * 64;
      int grow = row0 + rr; if (grow >= N) grow = N - 1;
      cp16(sb + rr * 80 + q * 16, Ah + (size_t)grow * K + k0 + q * 8);
      cp16(sb + 10240 + rr * 80 + q * 16, Al + (size_t)grow * K + k0 + q * 8);
    }
#pragma unroll
    for (int p = 0; p < BN / 64; ++p) {
      int rr = r + p * 64;
      int gc = col0 + rr;
      cp16(sb + 20480 + rr * 80 + q * 16, Bh + (size_t)gc * K + k0 + q * 8);
      cp16(sb + 20480 + SB + rr * 80 + q * 16, Bl + (size_t)gc * K + k0 + q * 8);
    }
  };

  load_stage(0, 0);
  cp_commit();
  for (int it = 0; it < NIT; ++it) {
    if (it + 1 < NIT) {
      load_stage((it + 1) & 1, (it + 1) * 32);
      cp_commit();
      cp_wait<1>();
    } else {
      cp_wait<0>();
    }
    __syncthreads();
    uint32_t sbu = smu + (uint32_t)(it & 1) * ST;
#pragma unroll
    for (int ka = 0; ka < 2; ++ka) {
      uint32_t ah[2][4], al[2][4];
#pragma unroll
      for (int ma = 0; ma < 2; ++ma) {
        uint32_t base = sbu + a_rel + (uint32_t)ma * 1280u + (uint32_t)ka * 32u;
        LDM4(ah[ma], base);
        LDM4(al[ma], base + 10240u);
      }
#pragma unroll
      for (int p = 0; p < NP; ++p) {
        uint32_t base = sbu + b_rel + (uint32_t)p * (16u * 80u) + (uint32_t)ka * 32u;
        uint32_t rb[4], rl[4];
        LDM4(rb, base);
        LDM4(rl, base + (uint32_t)SB);
#pragma unroll
        for (int ma = 0; ma < 2; ++ma) {
          MMA_BF16(c[ma][2 * p],     ah[ma], rb[0], rb[1]);
          MMA_BF16(c[ma][2 * p],     al[ma], rb[0], rb[1]);
          MMA_BF16(c[ma][2 * p],     ah[ma], rl[0], rl[1]);
          MMA_BF16(c[ma][2 * p + 1], ah[ma], rb[2], rb[3]);
          MMA_BF16(c[ma][2 * p + 1], al[ma], rb[2], rb[3]);
          MMA_BF16(c[ma][2 * p + 1], ah[ma], rl[2], rl[3]);
        }
      }
    }
    __syncthreads();
  }

  const int gq = lane >> 2, tq = lane & 3;
#pragma unroll
  for (int ma = 0; ma < 2; ++ma) {
    int row = row0 + wm * 32 + ma * 16 + gq;
#pragma unroll
    for (int na = 0; na < NA; ++na) {
      int col = col0 + wn * (BN / 2) + na * 8 + tq * 2;
      if (row < N)
        *(float2*)(C + (size_t)row * Fout + col) =
            make_float2(c[ma][na][0], c[ma][na][1]);
      if (row + 8 < N)
        *(float2*)(C + (size_t)(row + 8) * Fout + col) =
            make_float2(c[ma][na][2], c[ma][na][3]);
    }
  }
}

// -------------- CSR gather + fused bias/lrelu/bf16-split --------------------
template<int F>
__global__ void gather_split_kernel(const float* __restrict__ tmp,
                                    const float* __restrict__ bias,
                                    __nv_bfloat16* __restrict__ oh,
                                    __nv_bfloat16* __restrict__ ol, int n) {
  int w = (blockIdx.x * blockDim.x + threadIdx.x) >> 5;
  int lane = threadIdx.x & 31;
  if (w >= n) return;
  int beg = g_off[w], end = g_off[w + 1];
  float dr = g_dinv[w];
  constexpr int NV = F / 128;
  float4 acc[NV];
  const float4* self = (const float4*)(tmp + (size_t)w * F);
#pragma unroll
  for (int v = 0; v < NV; ++v) {
    float4 x = self[lane + 32 * v];
    acc[v] = make_float4(x.x * dr, x.y * dr, x.z * dr, x.w * dr);
  }
  for (int e0 = beg; e0 < end; e0 += 32) {
    int ne = min(32, end - e0);
    int s = 0; float ww = 0.f;
    if (lane < ne) { s = g_csr_src[e0 + lane]; ww = g_csr_w[e0 + lane]; }
    for (int j = 0; j < ne; ++j) {
      int sj = __shfl_sync(0xffffffffu, s, j);
      float wj = __shfl_sync(0xffffffffu, ww, j);
      const float4* sr = (const float4*)(tmp + (size_t)sj * F);
#pragma unroll
      for (int v = 0; v < NV; ++v) {
        float4 x = sr[lane + 32 * v];
        acc[v].x += wj * x.x; acc[v].y += wj * x.y;
        acc[v].z += wj * x.z; acc[v].w += wj * x.w;
      }
    }
  }
  uint32_t* ph = (uint32_t*)(oh + (size_t)w * F);
  uint32_t* pl = (uint32_t*)(ol + (size_t)w * F);
#pragma unroll
  for (int v = 0; v < NV; ++v) {
    int cb = lane + 32 * v;
    float4 b = *(const float4*)(bias + 4 * cb);
    float4 z = make_float4(acc[v].x * dr + b.x, acc[v].y * dr + b.y,
                           acc[v].z * dr + b.z, acc[v].w * dr + b.w);
    z.x = z.x > 0.f ? z.x : 0.01f * z.x;
    z.y = z.y > 0.f ? z.y : 0.01f * z.y;
    z.z = z.z > 0.f ? z.z : 0.01f * z.z;
    z.w = z.w > 0.f ? z.w : 0.01f * z.w;
    __nv_bfloat16 hx = __float2bfloat16(z.x), hy = __float2bfloat16(z.y);
    __nv_bfloat16 hz = __float2bfloat16(z.z), hw = __float2bfloat16(z.w);
    ph[2 * cb + 0] = pack_bf2(hx, hy);
    ph[2 * cb + 1] = pack_bf2(hz, hw);
    pl[2 * cb + 0] = pack_bf2(__float2bfloat16(z.x - __bfloat162float(hx)),
                              __float2bfloat16(z.y - __bfloat162float(hy)));
    pl[2 * cb + 1] = pack_bf2(__float2bfloat16(z.z - __bfloat162float(hz)),
                              __float2bfloat16(z.w - __bfloat162float(hw)));
  }
}

// ------------------- dropout (JAX threefry) -------------------------
#define TF_ROUND(x0, x1, r)                         \
  { x0 += x1; x1 = (x1 << (r)) | (x1 >> (32 - (r))); x1 ^= x0; }

__device__ __forceinline__ uint32_t threefry_bits(uint32_t idx) {
  const uint32_t k0 = 0u, k1 = 42u;
  const uint32_t k2 = 0x1BD11BDAu ^ k0 ^ k1;
  uint32_t x0 = 0u, x1 = idx;
  x0 += k0; x1 += k1;
  TF_ROUND(x0, x1, 13) TF_ROUND(x0, x1, 15) TF_ROUND(x0, x1, 26) TF_ROUND(x0, x1, 6)
  x0 += k1; x1 += k2 + 1u;
  TF_ROUND(x0, x1, 17) TF_ROUND(x0, x1, 29) TF_ROUND(x0, x1, 16) TF_ROUND(x0, x1, 24)
  x0 += k2; x1 += k0 + 2u;
  TF_ROUND(x0, x1, 13) TF_ROUND(x0, x1, 15) TF_ROUND(x0, x1, 26) TF_ROUND(x0, x1, 6)
  x0 += k0; x1 += k1 + 3u;
  TF_ROUND(x0, x1, 17) TF_ROUND(x0, x1, 29) TF_ROUND(x0, x1, 16) TF_ROUND(x0, x1, 24)
  x0 += k1; x1 += k2 + 4u;
  TF_ROUND(x0, x1, 13) TF_ROUND(x0, x1, 15) TF_ROUND(x0, x1, 26) TF_ROUND(x0, x1, 6)
  x0 += k2; x1 += k0 + 5u;
  return x0 ^ x1;
}

// L4 gather fused with bias4 + lrelu + dropout + dense 64->10.
__global__ void gather_final_kernel(const float* __restrict__ tmp,
                                    const float* __restrict__ b4,
                                    const float* __restrict__ W5,
                                    const float* __restrict__ b5,
                                    float* __restrict__ out, int n) {
  __shared__ float w5s[640];
  __shared__ float b5s[16];
  for (int i = threadIdx.x; i < 640; i += blockDim.x) w5s[i] = W5[i];
  if (threadIdx.x < 10) b5s[threadIdx.x] = b5[threadIdx.x];
  __syncthreads();

  int w = (blockIdx.x * blockDim.x + threadIdx.x) >> 5;
  int lane = threadIdx.x & 31;
  if (w >= n) return;
  int beg = g_off[w], end = g_off[w + 1];
  float dr = g_dinv[w];
  float2 acc;
  {
    float2 x = ((const float2*)(tmp + (size_t)w * 64))[lane];
    acc = make_float2(x.x * dr, x.y * dr);
  }
  for (int e0 = beg; e0 < end; e0 += 32) {
    int ne = min(32, end - e0);
    int s = 0; float ww = 0.f;
    if (lane < ne) { s = g_csr_src[e0 + lane]; ww = g_csr_w[e0 + lane]; }
    for (int j = 0; j < ne; ++j) {
      int sj = __shfl_sync(0xffffffffu, s, j);
      float wj = __shfl_sync(0xffffffffu, ww, j);
      float2 x = ((const float2*)(tmp + (size_t)sj * 64))[lane];
      acc.x += wj * x.x; acc.y += wj * x.y;
    }
  }
  int f0 = 2 * lane, f1 = 2 * lane + 1;
  float v0 = acc.x * dr + b4[f0];
  v0 = (v0 > 0.f) ? v0 : 0.01f * v0;
  float v1 = acc.y * dr + b4[f1];
  v1 = (v1 > 0.f) ? v1 : 0.01f * v1;
  uint32_t bits0 = threefry_bits((uint32_t)(w * 64 + f0));
  uint32_t bits1 = threefry_bits((uint32_t)(w * 64 + f1));
  v0 = (bits0 & 0x80000000u) ? 0.f : v0 * 2.f;
  v1 = (bits1 & 0x80000000u) ? 0.f : v1 * 2.f;
#pragma unroll
  for (int j = 0; j < 10; ++j) {
    float p = v0 * w5s[f0 * 10 + j] + v1 * w5s[f1 * 10 + j];
#pragma unroll
    for (int off = 16; off; off >>= 1)
      p += __shfl_xor_sync(0xffffffffu, p, off);
    if (lane == 0) out[w * 10 + j] = p + b5s[j];
  }
}

// ------------------------------ launch -------------------------------------
extern "C" void kernel_launch(void* const* d_in, const int* in_sizes, int n_in,
                              void* d_out, int out_size) {
  const float* x = (const float*)d_in[0];
  const int* ei = (const int*)d_in[1];   // int32
  const float* W1 = (const float*)d_in[2];
  const float* b1 = (const float*)d_in[3];
  const float* W2 = (const float*)d_in[4];
  const float* b2 = (const float*)d_in[5];
  const float* W3 = (const float*)d_in[6];
  const float* b3 = (const float*)d_in[7];
  const float* W4 = (const float*)d_in[8];
  const float* b4 = (const float*)d_in[9];
  const float* W5 = (const float*)d_in[10];
  const float* b5 = (const float*)d_in[11];
  const int N = in_sizes[0] / 256;
  const int E = in_sizes[1] / 2;
  const int* src = ei;
  const int* dstp = ei + E;

  float* tmp = nullptr;
  __nv_bfloat16 *ah = nullptr, *al = nullptr, *wh = nullptr, *wl = nullptr;
  cudaGetSymbolAddress((void**)&tmp, g_tmp);
  cudaGetSymbolAddress((void**)&ah, g_ah);
  cudaGetSymbolAddress((void**)&al, g_al);
  cudaGetSymbolAddress((void**)&wh, g_wh);
  cudaGetSymbolAddress((void**)&wl, g_wl);

  constexpr int SM_128 = 2 * (20480 + 2 * 128 * 80);  // 81920
  constexpr int SM_64  = 2 * (20480 + 2 * 64 * 80);   // 61440
  cudaFuncSetAttribute(gemm_bf16_kernel<128>,
                       cudaFuncAttributeMaxDynamicSharedMemorySize, SM_128);
  cudaFuncSetAttribute(gemm_bf16_kernel<64>,
                       cudaFuncAttributeMaxDynamicSharedMemorySize, SM_64);

  // Side stream + fork/join events. Created ONCE on the first call (the
  // non-captured correctness run) so no resource creation happens during
  // graph capture; the fork/join event pattern is capture-legal. GPU work
  // per call is identical.
  static cudaStream_t s2 = nullptr;
  static cudaEvent_t ev_fork = nullptr, ev_join = nullptr;
  if (s2 == nullptr) {
    cudaStreamCreateWithFlags(&s2, cudaStreamNonBlocking);
    cudaEventCreateWithFlags(&ev_fork, cudaEventDisableTiming);
    cudaEventCreateWithFlags(&ev_join, cudaEventDisableTiming);
  }

  // ---- fork: CSR build on s2, overlapped with splits + L1 GEMM ----
  cudaEventRecord(ev_fork, 0);
  cudaStreamWaitEvent(s2, ev_fork, 0);

  deg_init_kernel<<<(N + 255) / 256, 256, 0, s2>>>(N);
  deg_count_kernel<<<(E + 255) / 256, 256, 0, s2>>>(dstp, E);
  int nblk = (N + SCAN_BLK - 1) / SCAN_BLK;
  scan1_kernel<<<nblk, SCAN_BLK, 0, s2>>>(N);
  scan2_kernel<<<1, 64, 0, s2>>>(nblk);
  scan3_kernel<<<(N + 256) / 256, 256, 0, s2>>>(N, E);
  fill_kernel<<<(E + 255) / 256, 256, 0, s2>>>(src, dstp, E);
  cudaEventRecord(ev_join, s2);

  // ---- main stream: operand splits + L1 GEMM ----
  split_x_kernel<<<(N * 256 + 255) / 256, 256>>>(x, ah, al, N * 256);
  split_wt_all_kernel<<<(172032 + 255) / 256, 256>>>(W1, W2, W3, W4, wh, wl);

  const int MB = (N + 127) / 128;       // 391
  const int GW = (N * 32 + 255) / 256;  // warp per row

  // L1: 256->256
  gemm_bf16_kernel<128><<<dim3(MB, 2), 256, SM_128>>>(
      ah, al, wh, wl, tmp, N, 256, 256);

  // join: gathers need the CSR
  cudaStreamWaitEvent(0, ev_join, 0);
  gather_split_kernel<256><<<GW, 256>>>(tmp, b1, ah, al, N);

  // L2: 256->256
  gemm_bf16_kernel<128><<<dim3(MB, 2), 256, SM_128>>>(
      ah, al, wh + 65536, wl + 65536, tmp, N, 256, 256);
  gather_split_kernel<256><<<GW, 256>>>(tmp, b2, ah, al, N);

  // L3: 256->128
  gemm_bf16_kernel<128><<<dim3(MB, 1), 256, SM_128>>>(
      ah, al, wh + 131072, wl + 131072, tmp, N, 256, 128);
  gather_split_kernel<128><<<GW, 256>>>(tmp, b3, ah, al, N);

  // L4: 128->64, gather fused with final epilogue
  gemm_bf16_kernel<64><<<dim3(MB, 1), 256, SM_64>>>(
      ah, al, wh + 163840, wl + 163840, tmp, N, 128, 64);
  gather_final_kernel<<<GW, 256>>>(tmp, b4, W5, b5, (float*)d_out, N);
}